// round 1
// baseline (speedup 1.0000x reference)
#include <cuda_runtime.h>

#define N_NODES 50000
#define N_EDGES 600000
#define ETOT    650000           // edges + self loops
#define D       128
#define H       4
#define C       32
#define LAYERS  4
#define LN_EPS  1e-5f
#define SLOPE   0.2f

// ---------------- scratch (device globals; no allocations) ----------------
__device__ float    g_x[N_NODES * D];        // current node features
__device__ float    g_xl[N_NODES * D];       // x @ Wl + bl
__device__ float    g_xr[N_NODES * D];       // x @ Wr + br
__device__ float    g_out[N_NODES * D];      // unnormalized aggregation
__device__ float    g_logits[(size_t)ETOT * H];
__device__ unsigned g_m[N_NODES * H];        // segment max (encoded)
__device__ float    g_denom[N_NODES * H];    // softmax denominator

// order-preserving float<->uint encoding for atomicMax
__device__ __forceinline__ unsigned fenc(float f) {
    unsigned u = __float_as_uint(f);
    return (u & 0x80000000u) ? ~u : (u | 0x80000000u);
}
__device__ __forceinline__ float fdec(unsigned e) {
    return (e & 0x80000000u) ? __uint_as_float(e & 0x7fffffffu)
                             : __uint_as_float(~e);
}

__device__ __forceinline__ float leaky(float v) {
    return v > 0.f ? v : v * SLOPE;
}

__device__ __forceinline__ void red_add_v4(float* addr, float4 v) {
    asm volatile("red.global.add.v4.f32 [%0], {%1, %2, %3, %4};"
                 :: "l"(addr), "f"(v.x), "f"(v.y), "f"(v.z), "f"(v.w)
                 : "memory");
}

__device__ __forceinline__ float warp_sum(float v) {
    #pragma unroll
    for (int o = 16; o > 0; o >>= 1) v += __shfl_xor_sync(0xffffffffu, v, o);
    return v;
}

// ---------------- kernel 0: embedding + input projection + LN + ReLU ----------------
__global__ void __launch_bounds__(128) k_embed_proj(
    const int* __restrict__ types, const float* __restrict__ emb,
    const float* __restrict__ Wp, const float* __restrict__ bp,
    const float* __restrict__ gp, const float* __restrict__ betap)
{
    int n = blockIdx.x;
    int t = threadIdx.x;
    int ty = types[n];

    float acc = bp[t];
    #pragma unroll
    for (int k = 0; k < 16; k++)
        acc += emb[ty * 16 + k] * Wp[k * D + t];

    // layernorm over 128
    __shared__ float s1[4], s2[4];
    int lane = t & 31, warp = t >> 5;
    float w1 = warp_sum(acc), w2 = warp_sum(acc * acc);
    if (lane == 0) { s1[warp] = w1; s2[warp] = w2; }
    __syncthreads();
    float sum = s1[0] + s1[1] + s1[2] + s1[3];
    float ssq = s2[0] + s2[1] + s2[2] + s2[3];
    float mu  = sum * (1.f / D);
    float var = ssq * (1.f / D) - mu * mu;
    float y = (acc - mu) * rsqrtf(var + LN_EPS) * gp[t] + betap[t];
    g_x[n * D + t] = fmaxf(y, 0.f);
}

// ---------------- per-layer clear ----------------
__global__ void __launch_bounds__(256) k_clear()
{
    int i = blockIdx.x * 256 + threadIdx.x;
    if (i < N_NODES * D) g_out[i] = 0.f;
    if (i < N_NODES * H) { g_m[i] = 0x007FFFFFu; g_denom[i] = 0.f; }
}

// ---------------- GEMM: Y = g_x @ W + b   (Y = g_xl or g_xr via blockIdx.y) --------
// tile 64 rows x 128 cols, 256 threads, micro 8x4 per thread
__global__ void __launch_bounds__(256) k_gemm(
    const float* __restrict__ W0, const float* __restrict__ B0,
    const float* __restrict__ W1, const float* __restrict__ B1)
{
    __shared__ float xs[64 * D];     // 32 KB
    __shared__ float ws[32 * D];     // 16 KB

    const float* W = blockIdx.y ? W1 : W0;
    const float* B = blockIdx.y ? B1 : B0;
    float*       Y = blockIdx.y ? g_xr : g_xl;

    int t = threadIdx.x, lane = t & 31, warp = t >> 5;
    int row0 = blockIdx.x * 64;

    // load X tile (64x128) as float4
    const float4* X4 = (const float4*)g_x;
    float4* xs4 = (float4*)xs;
    #pragma unroll
    for (int i = 0; i < 8; i++) {
        int idx = t + i * 256;            // 0..2047
        int r = idx >> 5, c4 = idx & 31;
        float4 v = make_float4(0.f, 0.f, 0.f, 0.f);
        if (row0 + r < N_NODES) v = X4[(row0 + r) * 32 + c4];
        xs4[idx] = v;
    }

    float acc[8][4];
    #pragma unroll
    for (int i = 0; i < 8; i++)
        acc[i][0] = acc[i][1] = acc[i][2] = acc[i][3] = 0.f;

    const float4* W4 = (const float4*)W;
    float4* ws4 = (float4*)ws;

    for (int kc = 0; kc < 4; kc++) {
        __syncthreads();
        #pragma unroll
        for (int i = 0; i < 4; i++) {
            int idx = t + i * 256;        // 0..1023
            ws4[idx] = W4[kc * 1024 + idx];
        }
        __syncthreads();
        #pragma unroll
        for (int k = 0; k < 32; k++) {
            float4 w4 = ws4[k * 32 + lane];
            #pragma unroll
            for (int i = 0; i < 8; i++) {
                float xv = xs[(warp * 8 + i) * D + kc * 32 + k];
                acc[i][0] += xv * w4.x;
                acc[i][1] += xv * w4.y;
                acc[i][2] += xv * w4.z;
                acc[i][3] += xv * w4.w;
            }
        }
    }

    float4 bb = ((const float4*)B)[lane];
    #pragma unroll
    for (int i = 0; i < 8; i++) {
        int r = row0 + warp * 8 + i;
        if (r < N_NODES) {
            float4 o;
            o.x = acc[i][0] + bb.x; o.y = acc[i][1] + bb.y;
            o.z = acc[i][2] + bb.z; o.w = acc[i][3] + bb.w;
            ((float4*)Y)[r * 32 + lane] = o;
        }
    }
}

// ---------------- edge pass 1: logits + segment max ----------------
// one warp per edge; lane l covers channels [4l,4l+4); head = l>>3
__global__ void __launch_bounds__(256) k_edge_logits(
    const int* __restrict__ src, const int* __restrict__ dst,
    const float* __restrict__ att)
{
    int w = (blockIdx.x * 256 + threadIdx.x) >> 5;
    int lane = threadIdx.x & 31;
    if (w >= ETOT) return;
    int s, d;
    if (w < N_EDGES) { s = src[w]; d = dst[w]; }
    else             { s = w - N_EDGES; d = s; }

    const float4* xl4 = (const float4*)g_xl;
    const float4* xr4 = (const float4*)g_xr;
    float4 a = xl4[s * 32 + lane];
    float4 b = xr4[d * 32 + lane];
    float4 at = ((const float4*)att)[lane];

    float p = leaky(a.x + b.x) * at.x + leaky(a.y + b.y) * at.y
            + leaky(a.z + b.z) * at.z + leaky(a.w + b.w) * at.w;
    p += __shfl_xor_sync(0xffffffffu, p, 4);
    p += __shfl_xor_sync(0xffffffffu, p, 2);
    p += __shfl_xor_sync(0xffffffffu, p, 1);

    if ((lane & 7) == 0) {
        int h = lane >> 3;
        g_logits[(size_t)w * H + h] = p;
        atomicMax(&g_m[d * H + h], fenc(p));
    }
}

// ---------------- edge pass 2: unnormalized aggregation ----------------
__global__ void __launch_bounds__(256) k_edge_aggr(
    const int* __restrict__ src, const int* __restrict__ dst)
{
    int w = (blockIdx.x * 256 + threadIdx.x) >> 5;
    int lane = threadIdx.x & 31;
    if (w >= ETOT) return;
    int s, d;
    if (w < N_EDGES) { s = src[w]; d = dst[w]; }
    else             { s = w - N_EDGES; d = s; }

    int h = lane >> 3;
    float logit = g_logits[(size_t)w * H + h];
    float m = fdec(g_m[d * H + h]);
    float wgt = __expf(logit - m);

    const float4* xl4 = (const float4*)g_xl;
    float4 a = xl4[s * 32 + lane];
    float4 v = make_float4(a.x * wgt, a.y * wgt, a.z * wgt, a.w * wgt);
    red_add_v4(&g_out[d * D + lane * 4], v);

    if ((lane & 7) == 0) atomicAdd(&g_denom[d * H + h], wgt);
}

// ---------------- epilogue: normalize + bias + residual + LN + ReLU ----------------
__global__ void __launch_bounds__(128) k_epilogue(
    const float* __restrict__ gat_bias, const float* __restrict__ lng,
    const float* __restrict__ lnb, float* __restrict__ final_out, int last)
{
    int n = blockIdx.x;
    int t = threadIdx.x;

    float den = g_denom[n * H + (t >> 5)];
    float v = g_out[n * D + t] / den + gat_bias[t] + g_x[n * D + t];

    __shared__ float s1[4], s2[4];
    int lane = t & 31, warp = t >> 5;
    float w1 = warp_sum(v), w2 = warp_sum(v * v);
    if (lane == 0) { s1[warp] = w1; s2[warp] = w2; }
    __syncthreads();
    float sum = s1[0] + s1[1] + s1[2] + s1[3];
    float ssq = s2[0] + s2[1] + s2[2] + s2[3];
    float mu  = sum * (1.f / D);
    float var = ssq * (1.f / D) - mu * mu;
    float y = (v - mu) * rsqrtf(var + LN_EPS) * lng[t] + lnb[t];
    y = fmaxf(y, 0.f);

    if (last) final_out[n * D + t] = y;
    else      g_x[n * D + t] = y;
}

// ---------------- launch ----------------
extern "C" void kernel_launch(void* const* d_in, const int* in_sizes, int n_in,
                              void* d_out, int out_size)
{
    const int*   node_types = (const int*)d_in[0];
    const int*   edge_index = (const int*)d_in[1];
    const int*   src  = edge_index;
    const int*   dst  = edge_index + N_EDGES;
    const float* emb   = (const float*)d_in[2];
    const float* pW    = (const float*)d_in[3];
    const float* pb    = (const float*)d_in[4];
    const float* pg    = (const float*)d_in[5];
    const float* pbeta = (const float*)d_in[6];
    const float* Wl    = (const float*)d_in[7];
    const float* bl    = (const float*)d_in[8];
    const float* Wr    = (const float*)d_in[9];
    const float* br    = (const float*)d_in[10];
    const float* att   = (const float*)d_in[11];
    const float* gbias = (const float*)d_in[12];
    const float* lng   = (const float*)d_in[13];
    const float* lnb   = (const float*)d_in[14];
    float* out = (float*)d_out;

    k_embed_proj<<<N_NODES, 128>>>(node_types, emb, pW, pb, pg, pbeta);

    const int clear_blocks = (N_NODES * D + 255) / 256;
    const int gemm_blocks  = (N_NODES + 63) / 64;
    const int edge_blocks  = (ETOT * 32 + 255) / 256;

    for (int l = 0; l < LAYERS; l++) {
        k_clear<<<clear_blocks, 256>>>();
        k_gemm<<<dim3(gemm_blocks, 2), 256>>>(
            Wl + (size_t)l * D * D, bl + l * D,
            Wr + (size_t)l * D * D, br + l * D);
        k_edge_logits<<<edge_blocks, 256>>>(src, dst, att + l * H * C);
        k_edge_aggr<<<edge_blocks, 256>>>(src, dst);
        k_epilogue<<<N_NODES, 128>>>(gbias + l * D, lng + l * D, lnb + l * D,
                                     out, l == LAYERS - 1);
    }
}

// round 2
// speedup vs baseline: 1.8867x; 1.8867x over previous
#include <cuda_runtime.h>

#define N_NODES 50000
#define N_EDGES 600000
#define ETOT    650000           // edges + self loops
#define D       128
#define H       4
#define C       32
#define LAYERS  4
#define LN_EPS  1e-5f
#define SLOPE   0.2f

// ---------------- scratch (device globals; no allocations) ----------------
__device__ float g_x[N_NODES * D];        // current node features
__device__ float g_xl[N_NODES * D];       // x @ Wl + bl
__device__ float g_xr[N_NODES * D];       // x @ Wr + br
__device__ int   g_deg[N_NODES];          // degree (incl. self loop)
__device__ int   g_rowptr[N_NODES + 1];
__device__ int   g_fill[N_NODES];
__device__ int   g_csr_src[ETOT];         // src node per CSR slot

__device__ __forceinline__ float leaky(float v) {
    return v > 0.f ? v : v * SLOPE;
}

__device__ __forceinline__ float warp_sum(float v) {
    #pragma unroll
    for (int o = 16; o > 0; o >>= 1) v += __shfl_xor_sync(0xffffffffu, v, o);
    return v;
}

// ---------------- kernel 0: embedding + input projection + LN + ReLU ----------------
__global__ void __launch_bounds__(128) k_embed_proj(
    const int* __restrict__ types, const float* __restrict__ emb,
    const float* __restrict__ Wp, const float* __restrict__ bp,
    const float* __restrict__ gp, const float* __restrict__ betap)
{
    int n = blockIdx.x;
    int t = threadIdx.x;
    int ty = types[n];

    float acc = bp[t];
    #pragma unroll
    for (int k = 0; k < 16; k++)
        acc += emb[ty * 16 + k] * Wp[k * D + t];

    __shared__ float s1[4], s2[4];
    int lane = t & 31, warp = t >> 5;
    float w1 = warp_sum(acc), w2 = warp_sum(acc * acc);
    if (lane == 0) { s1[warp] = w1; s2[warp] = w2; }
    __syncthreads();
    float sum = s1[0] + s1[1] + s1[2] + s1[3];
    float ssq = s2[0] + s2[1] + s2[2] + s2[3];
    float mu  = sum * (1.f / D);
    float var = ssq * (1.f / D) - mu * mu;
    float y = (acc - mu) * rsqrtf(var + LN_EPS) * gp[t] + betap[t];
    g_x[n * D + t] = fmaxf(y, 0.f);
}

// ---------------- CSR build ----------------
__global__ void __launch_bounds__(256) k_deg_init()
{
    int i = blockIdx.x * 256 + threadIdx.x;
    if (i < N_NODES) g_deg[i] = 1;        // self loop
}

__global__ void __launch_bounds__(256) k_hist(const int* __restrict__ dst)
{
    int i = blockIdx.x * 256 + threadIdx.x;
    if (i < N_EDGES) atomicAdd(&g_deg[dst[i]], 1);
}

// single-block exclusive scan over g_deg -> g_rowptr; also place self loop
// at slot rowptr[i] and set fill[i] = rowptr[i]+1.
__global__ void __launch_bounds__(1024) k_scan_build()
{
    __shared__ int swsum[32];
    __shared__ int scarry;
    int t = threadIdx.x, lane = t & 31, wid = t >> 5;
    if (t == 0) scarry = 0;
    __syncthreads();

    for (int base = 0; base < N_NODES; base += 1024) {
        int i = base + t;
        int v = (i < N_NODES) ? g_deg[i] : 0;
        int x = v;
        #pragma unroll
        for (int o = 1; o < 32; o <<= 1) {
            int y = __shfl_up_sync(0xffffffffu, x, o);
            if (lane >= o) x += y;
        }
        if (lane == 31) swsum[wid] = x;
        __syncthreads();
        if (wid == 0) {
            int z = swsum[lane];
            #pragma unroll
            for (int o = 1; o < 32; o <<= 1) {
                int y = __shfl_up_sync(0xffffffffu, z, o);
                if (lane >= o) z += y;
            }
            swsum[lane] = z;
        }
        __syncthreads();
        int excl = scarry + (wid ? swsum[wid - 1] : 0) + (x - v);
        if (i < N_NODES) {
            g_rowptr[i] = excl;
            g_csr_src[excl] = i;          // self loop first
            g_fill[i] = excl + 1;
        }
        __syncthreads();
        if (t == 0) scarry += swsum[31];
        __syncthreads();
    }
    if (t == 0) g_rowptr[N_NODES] = scarry;   // = ETOT
}

__global__ void __launch_bounds__(256) k_scatter(
    const int* __restrict__ src, const int* __restrict__ dst)
{
    int i = blockIdx.x * 256 + threadIdx.x;
    if (i >= N_EDGES) return;
    int d = dst[i];
    int p = atomicAdd(&g_fill[d], 1);
    g_csr_src[p] = src[i];
}

// ---------------- GEMM: Y = g_x @ W + b   (Y = g_xl or g_xr via blockIdx.y) --------
__global__ void __launch_bounds__(256) k_gemm(
    const float* __restrict__ W0, const float* __restrict__ B0,
    const float* __restrict__ W1, const float* __restrict__ B1)
{
    __shared__ float xs[64 * D];     // 32 KB
    __shared__ float ws[32 * D];     // 16 KB

    const float* W = blockIdx.y ? W1 : W0;
    const float* B = blockIdx.y ? B1 : B0;
    float*       Y = blockIdx.y ? g_xr : g_xl;

    int t = threadIdx.x, lane = t & 31, warp = t >> 5;
    int row0 = blockIdx.x * 64;

    const float4* X4 = (const float4*)g_x;
    float4* xs4 = (float4*)xs;
    #pragma unroll
    for (int i = 0; i < 8; i++) {
        int idx = t + i * 256;            // 0..2047
        int r = idx >> 5, c4 = idx & 31;
        float4 v = make_float4(0.f, 0.f, 0.f, 0.f);
        if (row0 + r < N_NODES) v = X4[(row0 + r) * 32 + c4];
        xs4[idx] = v;
    }

    float acc[8][4];
    #pragma unroll
    for (int i = 0; i < 8; i++)
        acc[i][0] = acc[i][1] = acc[i][2] = acc[i][3] = 0.f;

    const float4* W4 = (const float4*)W;
    float4* ws4 = (float4*)ws;

    for (int kc = 0; kc < 4; kc++) {
        __syncthreads();
        #pragma unroll
        for (int i = 0; i < 4; i++) {
            int idx = t + i * 256;        // 0..1023
            ws4[idx] = W4[kc * 1024 + idx];
        }
        __syncthreads();
        #pragma unroll
        for (int k = 0; k < 32; k++) {
            float4 w4 = ws4[k * 32 + lane];
            #pragma unroll
            for (int i = 0; i < 8; i++) {
                float xv = xs[(warp * 8 + i) * D + kc * 32 + k];
                acc[i][0] += xv * w4.x;
                acc[i][1] += xv * w4.y;
                acc[i][2] += xv * w4.z;
                acc[i][3] += xv * w4.w;
            }
        }
    }

    float4 bb = ((const float4*)B)[lane];
    #pragma unroll
    for (int i = 0; i < 8; i++) {
        int r = row0 + warp * 8 + i;
        if (r < N_NODES) {
            float4 o;
            o.x = acc[i][0] + bb.x; o.y = acc[i][1] + bb.y;
            o.z = acc[i][2] + bb.z; o.w = acc[i][3] + bb.w;
            ((float4*)Y)[r * 32 + lane] = o;
        }
    }
}

// ---------------- fused GATv2 layer: warp per node, online softmax ----------------
// lane l covers channels [4l,4l+4); head = l>>3 (8 lanes per head)
__global__ void __launch_bounds__(256) k_gat(
    const float* __restrict__ att, const float* __restrict__ gat_bias,
    const float* __restrict__ lng, const float* __restrict__ lnb,
    float* __restrict__ final_out, int last)
{
    int n = (blockIdx.x * 256 + threadIdx.x) >> 5;
    int lane = threadIdx.x & 31;
    if (n >= N_NODES) return;

    const float4* xl4 = (const float4*)g_xl;
    float4 xr = ((const float4*)g_xr)[n * 32 + lane];
    float4 at = ((const float4*)att)[lane];

    int e0 = g_rowptr[n];
    int e1 = g_rowptr[n + 1];

    float m = -3.402823466e+38f;
    float s = 0.f;
    float4 acc = make_float4(0.f, 0.f, 0.f, 0.f);

    for (int e = e0; e < e1; e++) {
        int sidx = g_csr_src[e];
        float4 a = xl4[sidx * 32 + lane];
        float p = leaky(a.x + xr.x) * at.x + leaky(a.y + xr.y) * at.y
                + leaky(a.z + xr.z) * at.z + leaky(a.w + xr.w) * at.w;
        // sum over the 8 lanes of this head
        p += __shfl_xor_sync(0xffffffffu, p, 4);
        p += __shfl_xor_sync(0xffffffffu, p, 2);
        p += __shfl_xor_sync(0xffffffffu, p, 1);

        float nm = fmaxf(m, p);
        float wo = __expf(m - nm);
        float wn = __expf(p - nm);
        acc.x = acc.x * wo + a.x * wn;
        acc.y = acc.y * wo + a.y * wn;
        acc.z = acc.z * wo + a.z * wn;
        acc.w = acc.w * wo + a.w * wn;
        s = s * wo + wn;
        m = nm;
    }

    float inv = 1.f / s;
    float4 gb   = ((const float4*)gat_bias)[lane];
    float4 xres = ((const float4*)g_x)[n * 32 + lane];
    float4 v;
    v.x = acc.x * inv + gb.x + xres.x;
    v.y = acc.y * inv + gb.y + xres.y;
    v.z = acc.z * inv + gb.z + xres.z;
    v.w = acc.w * inv + gb.w + xres.w;

    // LayerNorm over the 128 channels this warp owns
    float sum = warp_sum(v.x + v.y + v.z + v.w);
    float ssq = warp_sum(v.x * v.x + v.y * v.y + v.z * v.z + v.w * v.w);
    float mu  = sum * (1.f / D);
    float var = ssq * (1.f / D) - mu * mu;
    float r   = rsqrtf(var + LN_EPS);

    float4 lg = ((const float4*)lng)[lane];
    float4 lb = ((const float4*)lnb)[lane];
    float4 y;
    y.x = fmaxf((v.x - mu) * r * lg.x + lb.x, 0.f);
    y.y = fmaxf((v.y - mu) * r * lg.y + lb.y, 0.f);
    y.z = fmaxf((v.z - mu) * r * lg.z + lb.z, 0.f);
    y.w = fmaxf((v.w - mu) * r * lg.w + lb.w, 0.f);

    float4* dstp = last ? (float4*)final_out : (float4*)g_x;
    dstp[n * 32 + lane] = y;
}

// ---------------- launch ----------------
extern "C" void kernel_launch(void* const* d_in, const int* in_sizes, int n_in,
                              void* d_out, int out_size)
{
    const int*   node_types = (const int*)d_in[0];
    const int*   edge_index = (const int*)d_in[1];
    const int*   src  = edge_index;
    const int*   dst  = edge_index + N_EDGES;
    const float* emb   = (const float*)d_in[2];
    const float* pW    = (const float*)d_in[3];
    const float* pb    = (const float*)d_in[4];
    const float* pg    = (const float*)d_in[5];
    const float* pbeta = (const float*)d_in[6];
    const float* Wl    = (const float*)d_in[7];
    const float* bl    = (const float*)d_in[8];
    const float* Wr    = (const float*)d_in[9];
    const float* br    = (const float*)d_in[10];
    const float* att   = (const float*)d_in[11];
    const float* gbias = (const float*)d_in[12];
    const float* lng   = (const float*)d_in[13];
    const float* lnb   = (const float*)d_in[14];
    float* out = (float*)d_out;

    k_embed_proj<<<N_NODES, 128>>>(node_types, emb, pW, pb, pg, pbeta);

    // CSR build (per call; reused across 4 layers)
    k_deg_init<<<(N_NODES + 255) / 256, 256>>>();
    k_hist<<<(N_EDGES + 255) / 256, 256>>>(dst);
    k_scan_build<<<1, 1024>>>();
    k_scatter<<<(N_EDGES + 255) / 256, 256>>>(src, dst);

    const int gemm_blocks = (N_NODES + 63) / 64;
    const int gat_blocks  = (N_NODES * 32 + 255) / 256;

    for (int l = 0; l < LAYERS; l++) {
        k_gemm<<<dim3(gemm_blocks, 2), 256>>>(
            Wl + (size_t)l * D * D, bl + l * D,
            Wr + (size_t)l * D * D, br + l * D);
        k_gat<<<gat_blocks, 256>>>(att + l * H * C, gbias + l * D,
                                   lng + l * D, lnb + l * D,
                                   out, l == LAYERS - 1);
    }
}

// round 4
// speedup vs baseline: 2.0273x; 1.0745x over previous
#include <cuda_runtime.h>
#include <cuda_bf16.h>
#include <cstdint>

#define N_NODES 50000
#define N_EDGES 600000
#define ETOT    650000           // edges + self loops
#define D       128
#define H       4
#define C       32
#define LAYERS  4
#define LN_EPS  1e-5f
#define SLOPE   0.2f
#define NB      196              // scan blocks: ceil(50000/256)
#define TSE     136              // padded smem row stride (bf16 elems)

// ---------------- scratch (device globals; no allocations) ----------------
__device__ float g_x[N_NODES * D];        // current node features
__device__ float g_xl[N_NODES * D];       // x @ Wl + bl
__device__ float g_xr[N_NODES * D];       // x @ Wr + br
__device__ int   g_deg[N_NODES];          // degree (incl. self loop)
__device__ int   g_rowptr[N_NODES + 1];
__device__ int   g_fill[N_NODES];
__device__ int   g_csr_src[ETOT];         // src node per CSR slot
__device__ int   g_bsum[256];             // scan block partials

__device__ __forceinline__ float leaky(float v) {
    return v > 0.f ? v : v * SLOPE;
}

__device__ __forceinline__ float warp_sum(float v) {
    #pragma unroll
    for (int o = 16; o > 0; o >>= 1) v += __shfl_xor_sync(0xffffffffu, v, o);
    return v;
}

__device__ __forceinline__ uint32_t smem_u32(const void* p) {
    uint32_t a;
    asm("{ .reg .u64 t; cvta.to.shared.u64 t, %1; cvt.u32.u64 %0, t; }"
        : "=r"(a) : "l"(p));
    return a;
}

// ---------------- tensor-core primitives (arch-portable PTX) ----------------
__device__ __forceinline__ void ldm4(uint32_t* r, uint32_t addr) {
    asm volatile("ldmatrix.sync.aligned.m8n8.x4.shared.b16 {%0,%1,%2,%3}, [%4];"
                 : "=r"(r[0]), "=r"(r[1]), "=r"(r[2]), "=r"(r[3]) : "r"(addr));
}

__device__ __forceinline__ void mma16816(float* d, const uint32_t* a,
                                         uint32_t b0, uint32_t b1) {
    asm volatile(
        "mma.sync.aligned.m16n8k16.row.col.f32.bf16.bf16.f32 "
        "{%0,%1,%2,%3}, {%4,%5,%6,%7}, {%8,%9}, {%0,%1,%2,%3};"
        : "+f"(d[0]), "+f"(d[1]), "+f"(d[2]), "+f"(d[3])
        : "r"(a[0]), "r"(a[1]), "r"(a[2]), "r"(a[3]), "r"(b0), "r"(b1));
}

// hi/lo bf16 split pack: 4 floats -> (hi 4xbf16 packed u2, lo 4xbf16 packed u2)
__device__ __forceinline__ void split4(float4 v, uint2& hp, uint2& lp) {
    __nv_bfloat16 h0 = __float2bfloat16_rn(v.x);
    __nv_bfloat16 h1 = __float2bfloat16_rn(v.y);
    __nv_bfloat16 h2 = __float2bfloat16_rn(v.z);
    __nv_bfloat16 h3 = __float2bfloat16_rn(v.w);
    __nv_bfloat16 l0 = __float2bfloat16_rn(v.x - __bfloat162float(h0));
    __nv_bfloat16 l1 = __float2bfloat16_rn(v.y - __bfloat162float(h1));
    __nv_bfloat16 l2 = __float2bfloat16_rn(v.z - __bfloat162float(h2));
    __nv_bfloat16 l3 = __float2bfloat16_rn(v.w - __bfloat162float(h3));
    hp.x = (uint32_t)__bfloat16_as_ushort(h0) | ((uint32_t)__bfloat16_as_ushort(h1) << 16);
    hp.y = (uint32_t)__bfloat16_as_ushort(h2) | ((uint32_t)__bfloat16_as_ushort(h3) << 16);
    lp.x = (uint32_t)__bfloat16_as_ushort(l0) | ((uint32_t)__bfloat16_as_ushort(l1) << 16);
    lp.y = (uint32_t)__bfloat16_as_ushort(l2) | ((uint32_t)__bfloat16_as_ushort(l3) << 16);
}

// ---------------- kernel 0: embedding + input projection + LN + ReLU ----------------
__global__ void __launch_bounds__(128) k_embed_proj(
    const int* __restrict__ types, const float* __restrict__ emb,
    const float* __restrict__ Wp, const float* __restrict__ bp,
    const float* __restrict__ gp, const float* __restrict__ betap)
{
    int n = blockIdx.x;
    int t = threadIdx.x;
    int ty = types[n];

    float acc = bp[t];
    #pragma unroll
    for (int k = 0; k < 16; k++)
        acc += emb[ty * 16 + k] * Wp[k * D + t];

    __shared__ float s1[4], s2[4];
    int lane = t & 31, warp = t >> 5;
    float w1 = warp_sum(acc), w2 = warp_sum(acc * acc);
    if (lane == 0) { s1[warp] = w1; s2[warp] = w2; }
    __syncthreads();
    float sum = s1[0] + s1[1] + s1[2] + s1[3];
    float ssq = s2[0] + s2[1] + s2[2] + s2[3];
    float mu  = sum * (1.f / D);
    float var = ssq * (1.f / D) - mu * mu;
    float y = (acc - mu) * rsqrtf(var + LN_EPS) * gp[t] + betap[t];
    g_x[n * D + t] = fmaxf(y, 0.f);
}

// ---------------- CSR build ----------------
__global__ void __launch_bounds__(256) k_deg_init()
{
    int i = blockIdx.x * 256 + threadIdx.x;
    if (i < N_NODES) g_deg[i] = 1;        // self loop
}

__global__ void __launch_bounds__(256) k_hist(const int* __restrict__ dst)
{
    int i = blockIdx.x * 256 + threadIdx.x;
    if (i < N_EDGES) atomicAdd(&g_deg[dst[i]], 1);
}

// phase 1: per-block scan; local exclusive -> g_rowptr, block total -> g_bsum
__global__ void __launch_bounds__(256) k_scan1()
{
    __shared__ int ws[8];
    int t = threadIdx.x, lane = t & 31, w = t >> 5;
    int i = blockIdx.x * 256 + t;
    int v = (i < N_NODES) ? g_deg[i] : 0;
    int x = v;
    #pragma unroll
    for (int o = 1; o < 32; o <<= 1) {
        int y = __shfl_up_sync(0xffffffffu, x, o);
        if (lane >= o) x += y;
    }
    if (lane == 31) ws[w] = x;
    __syncthreads();
    if (t == 0) {
        int run = 0;
        #pragma unroll
        for (int j = 0; j < 8; j++) { int tmp = ws[j]; ws[j] = run; run += tmp; }
        g_bsum[blockIdx.x] = run;
    }
    __syncthreads();
    if (i < N_NODES) g_rowptr[i] = ws[w] + (x - v);
}

// phase 2: exclusive scan of the 196 block sums (single small block)
__global__ void __launch_bounds__(256) k_scan2()
{
    __shared__ int ws[8];
    int t = threadIdx.x, lane = t & 31, w = t >> 5;
    int v = (t < NB) ? g_bsum[t] : 0;
    int x = v;
    #pragma unroll
    for (int o = 1; o < 32; o <<= 1) {
        int y = __shfl_up_sync(0xffffffffu, x, o);
        if (lane >= o) x += y;
    }
    if (lane == 31) ws[w] = x;
    __syncthreads();
    if (t == 0) {
        int run = 0;
        #pragma unroll
        for (int j = 0; j < 8; j++) { int tmp = ws[j]; ws[j] = run; run += tmp; }
        g_rowptr[N_NODES] = ETOT;
    }
    __syncthreads();
    g_bsum[t] = ws[w] + (x - v);
}

// phase 3: finalize rowptr, place self loops, init fill
__global__ void __launch_bounds__(256) k_build()
{
    int i = blockIdx.x * 256 + threadIdx.x;
    if (i >= N_NODES) return;
    int excl = g_rowptr[i] + g_bsum[i >> 8];
    g_rowptr[i] = excl;
    g_csr_src[excl] = i;                  // self loop first
    g_fill[i] = excl + 1;
}

__global__ void __launch_bounds__(256) k_scatter(
    const int* __restrict__ src, const int* __restrict__ dst)
{
    int i = blockIdx.x * 256 + threadIdx.x;
    if (i >= N_EDGES) return;
    int d = dst[i];
    int p = atomicAdd(&g_fill[d], 1);
    g_csr_src[p] = src[i];
}

// ---------------- HMMA GEMM: xl = X@Wl+bl, xr = X@Wr+br -------------------
// block: 128 rows, both sides computed sequentially (X tiles reused).
// smem: Xh, Xl, Wh, Wlo bf16 tiles 128 x TSE (34816B each; 139264 total).
// W tiles stored transposed [n][k] (k contiguous) for row.col mma.

__device__ __forceinline__ void fill_w(const float* __restrict__ W,
                                       __nv_bfloat16* Wh, __nv_bfloat16* Wlo,
                                       int tid)
{
    #pragma unroll
    for (int i = 0; i < 16; i++) {
        int idx = tid + i * 256;          // 0..4095
        int n  = idx & 127;
        int k0 = (idx >> 7) * 4;
        float4 v = make_float4(W[(k0 + 0) * D + n], W[(k0 + 1) * D + n],
                               W[(k0 + 2) * D + n], W[(k0 + 3) * D + n]);
        uint2 hp, lp;
        split4(v, hp, lp);
        *(uint2*)&Wh [n * TSE + k0] = hp;
        *(uint2*)&Wlo[n * TSE + k0] = lp;
    }
}

__device__ __forceinline__ void gemm_side(
    uint32_t xh_u, uint32_t xl_u, uint32_t wh_u, uint32_t wl_u,
    float* __restrict__ Y, const float* __restrict__ B,
    int row0, int wid, int lane)
{
    float acc[16][4];
    #pragma unroll
    for (int j = 0; j < 16; j++)
        #pragma unroll
        for (int q = 0; q < 4; q++) acc[j][q] = 0.f;

    int arow = lane & 15;
    int acol = (lane >> 4) << 3;          // 0 or 8
    int nrow = (lane & 7) + ((lane >> 4) << 3);
    int koff = lane & 8;

    #pragma unroll
    for (int prod = 0; prod < 3; prod++) {
        uint32_t abase = (prod == 2) ? xl_u : xh_u;
        uint32_t bbase = (prod == 1) ? wl_u : wh_u;
        uint32_t aaddr = abase + (uint32_t)(((wid * 16 + arow) * TSE + acol) * 2);
        uint32_t baddr = bbase + (uint32_t)((nrow * TSE + koff) * 2);
        #pragma unroll
        for (int ks = 0; ks < 8; ks++) {
            uint32_t a[4];
            ldm4(a, aaddr + ks * 32);
            uint32_t bb = baddr + ks * 32;
            #pragma unroll
            for (int jt = 0; jt < 8; jt++) {
                uint32_t b[4];
                ldm4(b, bb + jt * (16 * TSE * 2));
                mma16816(acc[jt * 2 + 0], a, b[0], b[1]);
                mma16816(acc[jt * 2 + 1], a, b[2], b[3]);
            }
        }
    }

    // epilogue: direct stores with bias
    int r0 = wid * 16 + (lane >> 2);
    int c0 = (lane & 3) * 2;
    #pragma unroll
    for (int jt = 0; jt < 16; jt++) {
        int col = jt * 8 + c0;
        float b0v = B[col], b1v = B[col + 1];
        int gr0 = row0 + r0;
        if (gr0 < N_NODES)
            *(float2*)&Y[gr0 * D + col] =
                make_float2(acc[jt][0] + b0v, acc[jt][1] + b1v);
        int gr1 = gr0 + 8;
        if (gr1 < N_NODES)
            *(float2*)&Y[gr1 * D + col] =
                make_float2(acc[jt][2] + b0v, acc[jt][3] + b1v);
    }
}

__global__ void __launch_bounds__(256) k_gemm_mma(
    const float* __restrict__ W_l, const float* __restrict__ B_l,
    const float* __restrict__ W_r, const float* __restrict__ B_r)
{
    extern __shared__ char sm[];
    __nv_bfloat16* Xh  = (__nv_bfloat16*)sm;
    __nv_bfloat16* Xlo = Xh  + 128 * TSE;
    __nv_bfloat16* Wh  = Xlo + 128 * TSE;
    __nv_bfloat16* Wlo = Wh  + 128 * TSE;

    int tid = threadIdx.x;
    int wid = tid >> 5, lane = tid & 31;
    int row0 = blockIdx.x * 128;

    // fill X tiles (hi/lo split)
    const float4* X4 = (const float4*)g_x;
    #pragma unroll
    for (int i = 0; i < 16; i++) {
        int idx = tid + i * 256;          // 0..4095
        int r = idx >> 5, kq = idx & 31;
        float4 v = make_float4(0.f, 0.f, 0.f, 0.f);
        if (row0 + r < N_NODES) v = X4[(row0 + r) * 32 + kq];
        uint2 hp, lp;
        split4(v, hp, lp);
        *(uint2*)&Xh [r * TSE + kq * 4] = hp;
        *(uint2*)&Xlo[r * TSE + kq * 4] = lp;
    }
    fill_w(W_l, Wh, Wlo, tid);
    __syncthreads();

    uint32_t xh_u = smem_u32(Xh),  xl_u = smem_u32(Xlo);
    uint32_t wh_u = smem_u32(Wh),  wl_u = smem_u32(Wlo);

    gemm_side(xh_u, xl_u, wh_u, wl_u, g_xl, B_l, row0, wid, lane);

    __syncthreads();
    fill_w(W_r, Wh, Wlo, tid);
    __syncthreads();

    gemm_side(xh_u, xl_u, wh_u, wl_u, g_xr, B_r, row0, wid, lane);
}

#define GEMM_SMEM (4 * 128 * TSE * 2)     // 139264

// ---------------- fused GATv2 layer: warp per node, online softmax ----------------
__global__ void __launch_bounds__(256) k_gat(
    const float* __restrict__ att, const float* __restrict__ gat_bias,
    const float* __restrict__ lng, const float* __restrict__ lnb,
    float* __restrict__ final_out, int last)
{
    int n = (blockIdx.x * 256 + threadIdx.x) >> 5;
    int lane = threadIdx.x & 31;
    if (n >= N_NODES) return;

    const float4* xl4 = (const float4*)g_xl;
    float4 xr = ((const float4*)g_xr)[n * 32 + lane];
    float4 at = ((const float4*)att)[lane];

    int e0 = g_rowptr[n];
    int e1 = g_rowptr[n + 1];

    float m = -3.402823466e+38f;
    float s = 0.f;
    float4 acc = make_float4(0.f, 0.f, 0.f, 0.f);

    int sidx = g_csr_src[e0];
    float4 a = xl4[sidx * 32 + lane];

    for (int e = e0; e < e1; e++) {
        float4 cur = a;
        if (e + 1 < e1) {
            int nx = g_csr_src[e + 1];
            a = xl4[nx * 32 + lane];
        }
        float p = leaky(cur.x + xr.x) * at.x + leaky(cur.y + xr.y) * at.y
                + leaky(cur.z + xr.z) * at.z + leaky(cur.w + xr.w) * at.w;
        p += __shfl_xor_sync(0xffffffffu, p, 4);
        p += __shfl_xor_sync(0xffffffffu, p, 2);
        p += __shfl_xor_sync(0xffffffffu, p, 1);

        float nm = fmaxf(m, p);
        float wo = __expf(m - nm);
        float wn = __expf(p - nm);
        acc.x = acc.x * wo + cur.x * wn;
        acc.y = acc.y * wo + cur.y * wn;
        acc.z = acc.z * wo + cur.z * wn;
        acc.w = acc.w * wo + cur.w * wn;
        s = s * wo + wn;
        m = nm;
    }

    float inv = 1.f / s;
    float4 gb   = ((const float4*)gat_bias)[lane];
    float4 xres = ((const float4*)g_x)[n * 32 + lane];
    float4 v;
    v.x = acc.x * inv + gb.x + xres.x;
    v.y = acc.y * inv + gb.y + xres.y;
    v.z = acc.z * inv + gb.z + xres.z;
    v.w = acc.w * inv + gb.w + xres.w;

    float sum = warp_sum(v.x + v.y + v.z + v.w);
    float ssq = warp_sum(v.x * v.x + v.y * v.y + v.z * v.z + v.w * v.w);
    float mu  = sum * (1.f / D);
    float var = ssq * (1.f / D) - mu * mu;
    float r   = rsqrtf(var + LN_EPS);

    float4 lg = ((const float4*)lng)[lane];
    float4 lb = ((const float4*)lnb)[lane];
    float4 y;
    y.x = fmaxf((v.x - mu) * r * lg.x + lb.x, 0.f);
    y.y = fmaxf((v.y - mu) * r * lg.y + lb.y, 0.f);
    y.z = fmaxf((v.z - mu) * r * lg.z + lb.z, 0.f);
    y.w = fmaxf((v.w - mu) * r * lg.w + lb.w, 0.f);

    float4* dstp = last ? (float4*)final_out : (float4*)g_x;
    dstp[n * 32 + lane] = y;
}

// ---------------- launch ----------------
extern "C" void kernel_launch(void* const* d_in, const int* in_sizes, int n_in,
                              void* d_out, int out_size)
{
    const int*   node_types = (const int*)d_in[0];
    const int*   edge_index = (const int*)d_in[1];
    const int*   src  = edge_index;
    const int*   dst  = edge_index + N_EDGES;
    const float* emb   = (const float*)d_in[2];
    const float* pW    = (const float*)d_in[3];
    const float* pb    = (const float*)d_in[4];
    const float* pg    = (const float*)d_in[5];
    const float* pbeta = (const float*)d_in[6];
    const float* Wl    = (const float*)d_in[7];
    const float* bl    = (const float*)d_in[8];
    const float* Wr    = (const float*)d_in[9];
    const float* br    = (const float*)d_in[10];
    const float* att   = (const float*)d_in[11];
    const float* gbias = (const float*)d_in[12];
    const float* lng   = (const float*)d_in[13];
    const float* lnb   = (const float*)d_in[14];
    float* out = (float*)d_out;

    cudaFuncSetAttribute(k_gemm_mma, cudaFuncAttributeMaxDynamicSharedMemorySize,
                         GEMM_SMEM);

    k_embed_proj<<<N_NODES, 128>>>(node_types, emb, pW, pb, pg, pbeta);

    // CSR build
    k_deg_init<<<NB, 256>>>();
    k_hist<<<(N_EDGES + 255) / 256, 256>>>(dst);
    k_scan1<<<NB, 256>>>();
    k_scan2<<<1, 256>>>();
    k_build<<<NB, 256>>>();
    k_scatter<<<(N_EDGES + 255) / 256, 256>>>(src, dst);

    const int gemm_blocks = (N_NODES + 127) / 128;   // 391
    const int gat_blocks  = (N_NODES * 32 + 255) / 256;

    for (int l = 0; l < LAYERS; l++) {
        k_gemm_mma<<<gemm_blocks, 256, GEMM_SMEM>>>(
            Wl + (size_t)l * D * D, bl + l * D,
            Wr + (size_t)l * D * D, br + l * D);
        k_gat<<<gat_blocks, 256>>>(att + l * H * C, gbias + l * D,
                                   lng + l * D, lnb + l * D,
                                   out, l == LAYERS - 1);
    }
}

// round 5
// speedup vs baseline: 2.4451x; 1.2061x over previous
#include <cuda_runtime.h>
#include <cuda_bf16.h>
#include <cstdint>

#define N_NODES 50000
#define N_EDGES 600000
#define ETOT    650000           // edges + self loops
#define D       128
#define H       4
#define C       32
#define LAYERS  4
#define LN_EPS  1e-5f
#define SLOPE   0.2f
#define NB      196              // scan blocks: ceil(50000/256)
#define TSE     136              // padded smem row stride (bf16 elems)

// ---------------- scratch (device globals; no allocations) ----------------
__device__ float g_x[N_NODES * D];        // current node features
__device__ float g_xl[N_NODES * D];       // x @ Wl + bl
__device__ float g_xr[N_NODES * D];       // x @ Wr + br
__device__ int   g_deg[N_NODES];          // degree (incl. self loop)
__device__ int   g_rowptr[N_NODES + 1];
__device__ int   g_fill[N_NODES];
__device__ int   g_csr_src[ETOT];         // src node per CSR slot
__device__ int   g_bsum[256];             // scan block partials
// pre-tiled weights: [layer][side][hi/lo][n*128+k], value = W[k*D+n]
__device__ __nv_bfloat16 g_wt[LAYERS][2][2][D * D];

__device__ __forceinline__ float leaky(float v) {
    return v > 0.f ? v : v * SLOPE;
}

__device__ __forceinline__ float warp_sum(float v) {
    #pragma unroll
    for (int o = 16; o > 0; o >>= 1) v += __shfl_xor_sync(0xffffffffu, v, o);
    return v;
}

__device__ __forceinline__ uint32_t smem_u32(const void* p) {
    uint32_t a;
    asm("{ .reg .u64 t; cvta.to.shared.u64 t, %1; cvt.u32.u64 %0, t; }"
        : "=r"(a) : "l"(p));
    return a;
}

// ---------------- tensor-core primitives (arch-portable PTX) ----------------
__device__ __forceinline__ void ldm4(uint32_t* r, uint32_t addr) {
    asm volatile("ldmatrix.sync.aligned.m8n8.x4.shared.b16 {%0,%1,%2,%3}, [%4];"
                 : "=r"(r[0]), "=r"(r[1]), "=r"(r[2]), "=r"(r[3]) : "r"(addr));
}

__device__ __forceinline__ void mma16816(float* d, const uint32_t* a,
                                         uint32_t b0, uint32_t b1) {
    asm volatile(
        "mma.sync.aligned.m16n8k16.row.col.f32.bf16.bf16.f32 "
        "{%0,%1,%2,%3}, {%4,%5,%6,%7}, {%8,%9}, {%0,%1,%2,%3};"
        : "+f"(d[0]), "+f"(d[1]), "+f"(d[2]), "+f"(d[3])
        : "r"(a[0]), "r"(a[1]), "r"(a[2]), "r"(a[3]), "r"(b0), "r"(b1));
}

// hi/lo bf16 split pack
__device__ __forceinline__ void split4(float4 v, uint2& hp, uint2& lp) {
    __nv_bfloat16 h0 = __float2bfloat16_rn(v.x);
    __nv_bfloat16 h1 = __float2bfloat16_rn(v.y);
    __nv_bfloat16 h2 = __float2bfloat16_rn(v.z);
    __nv_bfloat16 h3 = __float2bfloat16_rn(v.w);
    __nv_bfloat16 l0 = __float2bfloat16_rn(v.x - __bfloat162float(h0));
    __nv_bfloat16 l1 = __float2bfloat16_rn(v.y - __bfloat162float(h1));
    __nv_bfloat16 l2 = __float2bfloat16_rn(v.z - __bfloat162float(h2));
    __nv_bfloat16 l3 = __float2bfloat16_rn(v.w - __bfloat162float(h3));
    hp.x = (uint32_t)__bfloat16_as_ushort(h0) | ((uint32_t)__bfloat16_as_ushort(h1) << 16);
    hp.y = (uint32_t)__bfloat16_as_ushort(h2) | ((uint32_t)__bfloat16_as_ushort(h3) << 16);
    lp.x = (uint32_t)__bfloat16_as_ushort(l0) | ((uint32_t)__bfloat16_as_ushort(l1) << 16);
    lp.y = (uint32_t)__bfloat16_as_ushort(l2) | ((uint32_t)__bfloat16_as_ushort(l3) << 16);
}

// ---------------- W prep (all layers) + deg init ----------------
// grid 128 x 256: 32768 threads; each handles 4 consecutive k of one (l,s,n)
__global__ void __launch_bounds__(256) k_wprep_deg(const float* __restrict__ Wl,
                                                   const float* __restrict__ Wr)
{
    int t = blockIdx.x * 256 + threadIdx.x;     // 0..32767
    // deg init (50000 over 32768 threads -> 2 strided passes)
    if (t < N_NODES) g_deg[t] = 1;
    int t2 = t + 32768;
    if (t2 < N_NODES) g_deg[t2] = 1;

    // each thread: one (l, s, n, k0) quad; total = 4*2*128*32 = 32768
    int k0 = (t & 31) * 4;
    int n  = (t >> 5) & 127;
    int s  = (t >> 12) & 1;
    int l  = (t >> 13) & 3;
    const float* W = (s ? Wr : Wl) + (size_t)l * D * D;
    float4 v = make_float4(W[(k0 + 0) * D + n], W[(k0 + 1) * D + n],
                           W[(k0 + 2) * D + n], W[(k0 + 3) * D + n]);
    uint2 hp, lp;
    split4(v, hp, lp);
    *(uint2*)&g_wt[l][s][0][n * D + k0] = hp;
    *(uint2*)&g_wt[l][s][1][n * D + k0] = lp;
}

// ---------------- kernel 0: embedding + input projection + LN + ReLU ----------------
__global__ void __launch_bounds__(128) k_embed_proj(
    const int* __restrict__ types, const float* __restrict__ emb,
    const float* __restrict__ Wp, const float* __restrict__ bp,
    const float* __restrict__ gp, const float* __restrict__ betap)
{
    int n = blockIdx.x;
    int t = threadIdx.x;
    int ty = types[n];

    float acc = bp[t];
    #pragma unroll
    for (int k = 0; k < 16; k++)
        acc += emb[ty * 16 + k] * Wp[k * D + t];

    __shared__ float s1[4], s2[4];
    int lane = t & 31, warp = t >> 5;
    float w1 = warp_sum(acc), w2 = warp_sum(acc * acc);
    if (lane == 0) { s1[warp] = w1; s2[warp] = w2; }
    __syncthreads();
    float sum = s1[0] + s1[1] + s1[2] + s1[3];
    float ssq = s2[0] + s2[1] + s2[2] + s2[3];
    float mu  = sum * (1.f / D);
    float var = ssq * (1.f / D) - mu * mu;
    float y = (acc - mu) * rsqrtf(var + LN_EPS) * gp[t] + betap[t];
    g_x[n * D + t] = fmaxf(y, 0.f);
}

// ---------------- CSR build ----------------
__global__ void __launch_bounds__(256) k_hist(const int* __restrict__ dst)
{
    int i = blockIdx.x * 256 + threadIdx.x;
    if (i < N_EDGES) atomicAdd(&g_deg[dst[i]], 1);
}

__global__ void __launch_bounds__(256) k_scan1()
{
    __shared__ int ws[8];
    int t = threadIdx.x, lane = t & 31, w = t >> 5;
    int i = blockIdx.x * 256 + t;
    int v = (i < N_NODES) ? g_deg[i] : 0;
    int x = v;
    #pragma unroll
    for (int o = 1; o < 32; o <<= 1) {
        int y = __shfl_up_sync(0xffffffffu, x, o);
        if (lane >= o) x += y;
    }
    if (lane == 31) ws[w] = x;
    __syncthreads();
    if (t == 0) {
        int run = 0;
        #pragma unroll
        for (int j = 0; j < 8; j++) { int tmp = ws[j]; ws[j] = run; run += tmp; }
        g_bsum[blockIdx.x] = run;
    }
    __syncthreads();
    if (i < N_NODES) g_rowptr[i] = ws[w] + (x - v);
}

__global__ void __launch_bounds__(256) k_scan2()
{
    __shared__ int ws[8];
    int t = threadIdx.x, lane = t & 31, w = t >> 5;
    int v = (t < NB) ? g_bsum[t] : 0;
    int x = v;
    #pragma unroll
    for (int o = 1; o < 32; o <<= 1) {
        int y = __shfl_up_sync(0xffffffffu, x, o);
        if (lane >= o) x += y;
    }
    if (lane == 31) ws[w] = x;
    __syncthreads();
    if (t == 0) {
        int run = 0;
        #pragma unroll
        for (int j = 0; j < 8; j++) { int tmp = ws[j]; ws[j] = run; run += tmp; }
        g_rowptr[N_NODES] = ETOT;
    }
    __syncthreads();
    g_bsum[t] = ws[w] + (x - v);
}

__global__ void __launch_bounds__(256) k_build()
{
    int i = blockIdx.x * 256 + threadIdx.x;
    if (i >= N_NODES) return;
    int excl = g_rowptr[i] + g_bsum[i >> 8];
    g_rowptr[i] = excl;
    g_csr_src[excl] = i;                  // self loop first
    g_fill[i] = excl + 1;
}

__global__ void __launch_bounds__(256) k_scatter(
    const int* __restrict__ src, const int* __restrict__ dst)
{
    int i = blockIdx.x * 256 + threadIdx.x;
    if (i >= N_EDGES) return;
    int d = dst[i];
    int p = atomicAdd(&g_fill[d], 1);
    g_csr_src[p] = src[i];
}

// ---------------- HMMA GEMM: xl = X@Wl+bl AND xr = X@Wr+br in one pass -----------
// smem: Xh Xl Wlh Wll Wrh Wrl, 128 x TSE bf16 each (34816 B) -> 208896 B total.
// A fragments cached in registers across both sides and all products.
#define GEMM_SMEM (6 * 128 * TSE * 2)     // 208896

__device__ __forceinline__ void gemm_side(
    const uint32_t (*ah)[4], const uint32_t (*al)[4],
    uint32_t wh_u, uint32_t wl_u,
    float* __restrict__ Y, const float* __restrict__ B,
    int row0, int wid, int lane)
{
    float acc[16][4];
    #pragma unroll
    for (int j = 0; j < 16; j++)
        #pragma unroll
        for (int q = 0; q < 4; q++) acc[j][q] = 0.f;

    int nrow = (lane & 7) + ((lane >> 4) << 3);
    int koff = lane & 8;
    uint32_t bh_addr = wh_u + (uint32_t)((nrow * TSE + koff) * 2);
    uint32_t bl_addr = wl_u + (uint32_t)((nrow * TSE + koff) * 2);
    const uint32_t jstride = 16 * TSE * 2;

    #pragma unroll
    for (int ks = 0; ks < 8; ks++) {
        uint32_t bh[8][4], bl[8][4];
        #pragma unroll
        for (int jt = 0; jt < 8; jt++) ldm4(bh[jt], bh_addr + ks * 32 + jt * jstride);
        #pragma unroll
        for (int jt = 0; jt < 8; jt++) ldm4(bl[jt], bl_addr + ks * 32 + jt * jstride);
        // Ah * Bh
        #pragma unroll
        for (int jt = 0; jt < 8; jt++) {
            mma16816(acc[jt * 2 + 0], ah[ks], bh[jt][0], bh[jt][1]);
            mma16816(acc[jt * 2 + 1], ah[ks], bh[jt][2], bh[jt][3]);
        }
        // Al * Bh
        #pragma unroll
        for (int jt = 0; jt < 8; jt++) {
            mma16816(acc[jt * 2 + 0], al[ks], bh[jt][0], bh[jt][1]);
            mma16816(acc[jt * 2 + 1], al[ks], bh[jt][2], bh[jt][3]);
        }
        // Ah * Bl
        #pragma unroll
        for (int jt = 0; jt < 8; jt++) {
            mma16816(acc[jt * 2 + 0], ah[ks], bl[jt][0], bl[jt][1]);
            mma16816(acc[jt * 2 + 1], ah[ks], bl[jt][2], bl[jt][3]);
        }
    }

    // epilogue: direct stores with bias
    int r0 = wid * 16 + (lane >> 2);
    int c0 = (lane & 3) * 2;
    #pragma unroll
    for (int jt = 0; jt < 16; jt++) {
        int col = jt * 8 + c0;
        float b0v = B[col], b1v = B[col + 1];
        int gr0 = row0 + r0;
        if (gr0 < N_NODES)
            *(float2*)&Y[gr0 * D + col] =
                make_float2(acc[jt][0] + b0v, acc[jt][1] + b1v);
        int gr1 = gr0 + 8;
        if (gr1 < N_NODES)
            *(float2*)&Y[gr1 * D + col] =
                make_float2(acc[jt][2] + b0v, acc[jt][3] + b1v);
    }
}

__global__ void __launch_bounds__(256) k_gemm_mma(
    int layer, const float* __restrict__ B_l, const float* __restrict__ B_r)
{
    extern __shared__ char sm[];
    __nv_bfloat16* Xh  = (__nv_bfloat16*)sm;
    __nv_bfloat16* Xlo = Xh  + 128 * TSE;
    __nv_bfloat16* Wlh = Xlo + 128 * TSE;
    __nv_bfloat16* Wll = Wlh + 128 * TSE;
    __nv_bfloat16* Wrh = Wll + 128 * TSE;
    __nv_bfloat16* Wrl = Wrh + 128 * TSE;

    int tid = threadIdx.x;
    int wid = tid >> 5, lane = tid & 31;
    int row0 = blockIdx.x * 128;

    // fill X tiles (hi/lo split)
    const float4* X4 = (const float4*)g_x;
    #pragma unroll
    for (int i = 0; i < 16; i++) {
        int idx = tid + i * 256;          // 0..4095
        int r = idx >> 5, kq = idx & 31;
        float4 v = make_float4(0.f, 0.f, 0.f, 0.f);
        if (row0 + r < N_NODES) v = X4[(row0 + r) * 32 + kq];
        uint2 hp, lp;
        split4(v, hp, lp);
        *(uint2*)&Xh [r * TSE + kq * 4] = hp;
        *(uint2*)&Xlo[r * TSE + kq * 4] = lp;
    }
    // copy pre-tiled W (4 tiles of 16384 bf16 = 2048 uint4 each)
    {
        const uint4* wsrc = (const uint4*)&g_wt[layer][0][0][0];
        __nv_bfloat16* wdst[4] = { Wlh, Wll, Wrh, Wrl };
        #pragma unroll
        for (int tI = 0; tI < 4; tI++) {
            const uint4* sp = wsrc + tI * 2048;
            __nv_bfloat16* dp = wdst[tI];
            #pragma unroll
            for (int i = 0; i < 8; i++) {
                int e = tid + i * 256;            // uint4 index 0..2047
                int n = e >> 4, k0 = (e & 15) * 8;
                *(uint4*)&dp[n * TSE + k0] = sp[e];
            }
        }
    }
    __syncthreads();

    // cache A fragments (both hi and lo) in registers
    uint32_t ah[8][4], al[8][4];
    {
        int arow = lane & 15;
        int acol = (lane >> 4) << 3;
        uint32_t xh_u = smem_u32(Xh) + (uint32_t)(((wid * 16 + arow) * TSE + acol) * 2);
        uint32_t xl_u = smem_u32(Xlo) + (uint32_t)(((wid * 16 + arow) * TSE + acol) * 2);
        #pragma unroll
        for (int ks = 0; ks < 8; ks++) {
            ldm4(ah[ks], xh_u + ks * 32);
            ldm4(al[ks], xl_u + ks * 32);
        }
    }

    gemm_side(ah, al, smem_u32(Wlh), smem_u32(Wll), g_xl, B_l, row0, wid, lane);
    gemm_side(ah, al, smem_u32(Wrh), smem_u32(Wrl), g_xr, B_r, row0, wid, lane);
}

// ---------------- fused GATv2 layer: warp per node, online softmax ----------------
__global__ void __launch_bounds__(256) k_gat(
    const float* __restrict__ att, const float* __restrict__ gat_bias,
    const float* __restrict__ lng, const float* __restrict__ lnb,
    float* __restrict__ final_out, int last)
{
    int n = (blockIdx.x * 256 + threadIdx.x) >> 5;
    int lane = threadIdx.x & 31;
    if (n >= N_NODES) return;

    const float4* xl4 = (const float4*)g_xl;
    float4 xr = ((const float4*)g_xr)[n * 32 + lane];
    float4 at = ((const float4*)att)[lane];

    int e0 = g_rowptr[n];
    int e1 = g_rowptr[n + 1];

    float m = -3.402823466e+38f;
    float s = 0.f;
    float4 acc = make_float4(0.f, 0.f, 0.f, 0.f);

    int sidx = g_csr_src[e0];
    float4 a = xl4[sidx * 32 + lane];

    for (int e = e0; e < e1; e++) {
        float4 cur = a;
        if (e + 1 < e1) {
            int nx = g_csr_src[e + 1];
            a = xl4[nx * 32 + lane];
        }
        float p = leaky(cur.x + xr.x) * at.x + leaky(cur.y + xr.y) * at.y
                + leaky(cur.z + xr.z) * at.z + leaky(cur.w + xr.w) * at.w;
        p += __shfl_xor_sync(0xffffffffu, p, 4);
        p += __shfl_xor_sync(0xffffffffu, p, 2);
        p += __shfl_xor_sync(0xffffffffu, p, 1);

        float nm = fmaxf(m, p);
        float wo = __expf(m - nm);
        float wn = __expf(p - nm);
        acc.x = acc.x * wo + cur.x * wn;
        acc.y = acc.y * wo + cur.y * wn;
        acc.z = acc.z * wo + cur.z * wn;
        acc.w = acc.w * wo + cur.w * wn;
        s = s * wo + wn;
        m = nm;
    }

    float inv = 1.f / s;
    float4 gb   = ((const float4*)gat_bias)[lane];
    float4 xres = ((const float4*)g_x)[n * 32 + lane];
    float4 v;
    v.x = acc.x * inv + gb.x + xres.x;
    v.y = acc.y * inv + gb.y + xres.y;
    v.z = acc.z * inv + gb.z + xres.z;
    v.w = acc.w * inv + gb.w + xres.w;

    float sum = warp_sum(v.x + v.y + v.z + v.w);
    float ssq = warp_sum(v.x * v.x + v.y * v.y + v.z * v.z + v.w * v.w);
    float mu  = sum * (1.f / D);
    float var = ssq * (1.f / D) - mu * mu;
    float r   = rsqrtf(var + LN_EPS);

    float4 lg = ((const float4*)lng)[lane];
    float4 lb = ((const float4*)lnb)[lane];
    float4 y;
    y.x = fmaxf((v.x - mu) * r * lg.x + lb.x, 0.f);
    y.y = fmaxf((v.y - mu) * r * lg.y + lb.y, 0.f);
    y.z = fmaxf((v.z - mu) * r * lg.z + lb.z, 0.f);
    y.w = fmaxf((v.w - mu) * r * lg.w + lb.w, 0.f);

    float4* dstp = last ? (float4*)final_out : (float4*)g_x;
    dstp[n * 32 + lane] = y;
}

// ---------------- launch ----------------
extern "C" void kernel_launch(void* const* d_in, const int* in_sizes, int n_in,
                              void* d_out, int out_size)
{
    const int*   node_types = (const int*)d_in[0];
    const int*   edge_index = (const int*)d_in[1];
    const int*   src  = edge_index;
    const int*   dst  = edge_index + N_EDGES;
    const float* emb   = (const float*)d_in[2];
    const float* pW    = (const float*)d_in[3];
    const float* pb    = (const float*)d_in[4];
    const float* pg    = (const float*)d_in[5];
    const float* pbeta = (const float*)d_in[6];
    const float* Wl    = (const float*)d_in[7];
    const float* bl    = (const float*)d_in[8];
    const float* Wr    = (const float*)d_in[9];
    const float* br    = (const float*)d_in[10];
    const float* att   = (const float*)d_in[11];
    const float* gbias = (const float*)d_in[12];
    const float* lng   = (const float*)d_in[13];
    const float* lnb   = (const float*)d_in[14];
    float* out = (float*)d_out;

    cudaFuncSetAttribute(k_gemm_mma, cudaFuncAttributeMaxDynamicSharedMemorySize,
                         GEMM_SMEM);

    const int gemm_blocks = (N_NODES + 127) / 128;   // 391
    const int gat_blocks  = (N_NODES * 32 + 255) / 256;

    // launch order chosen so layer-0 GEMM is launch index 3 (profiled by ncu)
    k_wprep_deg<<<128, 256>>>(Wl, Wr);                       // 0: W tiles + deg init
    k_embed_proj<<<N_NODES, 128>>>(node_types, emb, pW, pb, pg, pbeta); // 1
    k_hist<<<(N_EDGES + 255) / 256, 256>>>(dst);             // 2
    k_gemm_mma<<<gemm_blocks, 256, GEMM_SMEM>>>(0, bl, br);  // 3  <-- profiled
    k_scan1<<<NB, 256>>>();                                  // 4
    k_scan2<<<1, 256>>>();                                   // 5
    k_build<<<NB, 256>>>();                                  // 6
    k_scatter<<<(N_EDGES + 255) / 256, 256>>>(src, dst);     // 7

    for (int l = 0; l < LAYERS; l++) {
        if (l > 0)
            k_gemm_mma<<<gemm_blocks, 256, GEMM_SMEM>>>(l, bl + l * D, br + l * D);
        k_gat<<<gat_blocks, 256>>>(att + l * H * C, gbias + l * D,
                                   lng + l * D, lnb + l * D,
                                   out, l == LAYERS - 1);
    }
}

// round 6
// speedup vs baseline: 2.6616x; 1.0885x over previous
#include <cuda_runtime.h>
#include <cuda_bf16.h>
#include <cstdint>

#define N_NODES 50000
#define N_EDGES 600000
#define ETOT    650000           // edges + self loops
#define D       128
#define H       4
#define C       32
#define LAYERS  4
#define LN_EPS  1e-5f
#define SLOPE   0.2f
#define NB      196              // scan blocks: ceil(50000/256)
#define TSE     136              // padded smem row stride (bf16 elems)

// ---------------- scratch (device globals; no allocations) ----------------
__device__ float g_x[N_NODES * D];        // current node features
__device__ float g_xl[N_NODES * D];       // x @ Wl + bl
__device__ float g_xr[N_NODES * D];       // x @ Wr + br
__device__ int   g_deg[N_NODES];          // degree (incl. self loop)
__device__ int   g_rowptr[N_NODES + 1];
__device__ int   g_fill[N_NODES];
__device__ int   g_csr_src[ETOT];         // src node per CSR slot
__device__ int   g_bsum[256];             // scan block partials
// pre-computed mma B-fragments: [l][s][ks][jt][hl][lane] -> uint4 (4 frag regs)
// per (l,s): 8*8*2*32 = 4096 uint4
__device__ uint4 g_wfrag[LAYERS * 2 * 4096];

__device__ __forceinline__ float leaky(float v) {
    return v > 0.f ? v : v * SLOPE;
}

__device__ __forceinline__ float warp_sum(float v) {
    #pragma unroll
    for (int o = 16; o > 0; o >>= 1) v += __shfl_xor_sync(0xffffffffu, v, o);
    return v;
}

__device__ __forceinline__ uint32_t smem_u32(const void* p) {
    uint32_t a;
    asm("{ .reg .u64 t; cvta.to.shared.u64 t, %1; cvt.u32.u64 %0, t; }"
        : "=r"(a) : "l"(p));
    return a;
}

// ---------------- tensor-core primitives (arch-portable PTX) ----------------
__device__ __forceinline__ void ldm4(uint32_t* r, uint32_t addr) {
    asm volatile("ldmatrix.sync.aligned.m8n8.x4.shared.b16 {%0,%1,%2,%3}, [%4];"
                 : "=r"(r[0]), "=r"(r[1]), "=r"(r[2]), "=r"(r[3]) : "r"(addr));
}

__device__ __forceinline__ void mma16816(float* d, const uint32_t* a,
                                         uint32_t b0, uint32_t b1) {
    asm volatile(
        "mma.sync.aligned.m16n8k16.row.col.f32.bf16.bf16.f32 "
        "{%0,%1,%2,%3}, {%4,%5,%6,%7}, {%8,%9}, {%0,%1,%2,%3};"
        : "+f"(d[0]), "+f"(d[1]), "+f"(d[2]), "+f"(d[3])
        : "r"(a[0]), "r"(a[1]), "r"(a[2]), "r"(a[3]), "r"(b0), "r"(b1));
}

// hi/lo bf16 split pack
__device__ __forceinline__ void split4(float4 v, uint2& hp, uint2& lp) {
    __nv_bfloat16 h0 = __float2bfloat16_rn(v.x);
    __nv_bfloat16 h1 = __float2bfloat16_rn(v.y);
    __nv_bfloat16 h2 = __float2bfloat16_rn(v.z);
    __nv_bfloat16 h3 = __float2bfloat16_rn(v.w);
    __nv_bfloat16 l0 = __float2bfloat16_rn(v.x - __bfloat162float(h0));
    __nv_bfloat16 l1 = __float2bfloat16_rn(v.y - __bfloat162float(h1));
    __nv_bfloat16 l2 = __float2bfloat16_rn(v.z - __bfloat162float(h2));
    __nv_bfloat16 l3 = __float2bfloat16_rn(v.w - __bfloat16_as_ushort(h3) * 0.f - __bfloat162float(h3));
    hp.x = (uint32_t)__bfloat16_as_ushort(h0) | ((uint32_t)__bfloat16_as_ushort(h1) << 16);
    hp.y = (uint32_t)__bfloat16_as_ushort(h2) | ((uint32_t)__bfloat16_as_ushort(h3) << 16);
    lp.x = (uint32_t)__bfloat16_as_ushort(l0) | ((uint32_t)__bfloat16_as_ushort(l1) << 16);
    lp.y = (uint32_t)__bfloat16_as_ushort(l2) | ((uint32_t)__bfloat16_as_ushort(l3) << 16);
}

// pack one (hi or lo) bf16 pair from two floats
__device__ __forceinline__ uint32_t pack_hl(float a, float b, int hl) {
    __nv_bfloat16 ha = __float2bfloat16_rn(a);
    __nv_bfloat16 hb = __float2bfloat16_rn(b);
    if (hl) {
        ha = __float2bfloat16_rn(a - __bfloat162float(ha));
        hb = __float2bfloat16_rn(b - __bfloat162float(hb));
    }
    return (uint32_t)__bfloat16_as_ushort(ha) |
           ((uint32_t)__bfloat16_as_ushort(hb) << 16);
}

// ---------------- W fragment prep (all layers) + deg init ----------------
// grid 128 x 256 = 32768 threads; thread = (l, s, ks, jt, hl, lane)
__global__ void __launch_bounds__(256) k_wprep_deg(const float* __restrict__ Wl,
                                                   const float* __restrict__ Wr)
{
    int t = blockIdx.x * 256 + threadIdx.x;     // 0..32767
    if (t < N_NODES) g_deg[t] = 1;
    int t2 = t + 32768;
    if (t2 < N_NODES) g_deg[t2] = 1;

    int lane = t & 31;
    int hl   = (t >> 5) & 1;
    int jt   = (t >> 6) & 7;
    int ks   = (t >> 9) & 7;
    int s    = (t >> 12) & 1;
    int l    = (t >> 13) & 3;

    const float* W = (s ? Wr : Wl) + (size_t)l * D * D;
    int n0 = jt * 16 + (lane >> 2);
    int k0 = ks * 16 + 2 * (lane & 3);
    // Wt[n][k] = W[k*D + n]; ldmatrix frag: reg j = matrix j (row lane/4, colpair)
    uint4 f;
    f.x = pack_hl(W[(k0 + 0) * D + n0],     W[(k0 + 1) * D + n0],     hl);
    f.y = pack_hl(W[(k0 + 8) * D + n0],     W[(k0 + 9) * D + n0],     hl);
    f.z = pack_hl(W[(k0 + 0) * D + n0 + 8], W[(k0 + 1) * D + n0 + 8], hl);
    f.w = pack_hl(W[(k0 + 8) * D + n0 + 8], W[(k0 + 9) * D + n0 + 8], hl);
    g_wfrag[(((((l * 2 + s) * 8 + ks) * 8 + jt) * 2 + hl) * 32) + lane] = f;
}

// ---------------- kernel 0: embedding + input projection + LN + ReLU ----------------
__global__ void __launch_bounds__(128) k_embed_proj(
    const int* __restrict__ types, const float* __restrict__ emb,
    const float* __restrict__ Wp, const float* __restrict__ bp,
    const float* __restrict__ gp, const float* __restrict__ betap)
{
    int n = blockIdx.x;
    int t = threadIdx.x;
    int ty = types[n];

    float acc = bp[t];
    #pragma unroll
    for (int k = 0; k < 16; k++)
        acc += emb[ty * 16 + k] * Wp[k * D + t];

    __shared__ float s1[4], s2[4];
    int lane = t & 31, warp = t >> 5;
    float w1 = warp_sum(acc), w2 = warp_sum(acc * acc);
    if (lane == 0) { s1[warp] = w1; s2[warp] = w2; }
    __syncthreads();
    float sum = s1[0] + s1[1] + s1[2] + s1[3];
    float ssq = s2[0] + s2[1] + s2[2] + s2[3];
    float mu  = sum * (1.f / D);
    float var = ssq * (1.f / D) - mu * mu;
    float y = (acc - mu) * rsqrtf(var + LN_EPS) * gp[t] + betap[t];
    g_x[n * D + t] = fmaxf(y, 0.f);
}

// ---------------- CSR build ----------------
__global__ void __launch_bounds__(256) k_hist(const int* __restrict__ dst)
{
    int i = blockIdx.x * 256 + threadIdx.x;
    if (i < N_EDGES) atomicAdd(&g_deg[dst[i]], 1);
}

__global__ void __launch_bounds__(256) k_scan1()
{
    __shared__ int ws[8];
    int t = threadIdx.x, lane = t & 31, w = t >> 5;
    int i = blockIdx.x * 256 + t;
    int v = (i < N_NODES) ? g_deg[i] : 0;
    int x = v;
    #pragma unroll
    for (int o = 1; o < 32; o <<= 1) {
        int y = __shfl_up_sync(0xffffffffu, x, o);
        if (lane >= o) x += y;
    }
    if (lane == 31) ws[w] = x;
    __syncthreads();
    if (t == 0) {
        int run = 0;
        #pragma unroll
        for (int j = 0; j < 8; j++) { int tmp = ws[j]; ws[j] = run; run += tmp; }
        g_bsum[blockIdx.x] = run;
    }
    __syncthreads();
    if (i < N_NODES) g_rowptr[i] = ws[w] + (x - v);
}

__global__ void __launch_bounds__(256) k_scan2()
{
    __shared__ int ws[8];
    int t = threadIdx.x, lane = t & 31, w = t >> 5;
    int v = (t < NB) ? g_bsum[t] : 0;
    int x = v;
    #pragma unroll
    for (int o = 1; o < 32; o <<= 1) {
        int y = __shfl_up_sync(0xffffffffu, x, o);
        if (lane >= o) x += y;
    }
    if (lane == 31) ws[w] = x;
    __syncthreads();
    if (t == 0) {
        int run = 0;
        #pragma unroll
        for (int j = 0; j < 8; j++) { int tmp = ws[j]; ws[j] = run; run += tmp; }
        g_rowptr[N_NODES] = ETOT;
    }
    __syncthreads();
    g_bsum[t] = ws[w] + (x - v);
}

__global__ void __launch_bounds__(256) k_build()
{
    int i = blockIdx.x * 256 + threadIdx.x;
    if (i >= N_NODES) return;
    int excl = g_rowptr[i] + g_bsum[i >> 8];
    g_rowptr[i] = excl;
    g_csr_src[excl] = i;                  // self loop first
    g_fill[i] = excl + 1;
}

__global__ void __launch_bounds__(256) k_scatter(
    const int* __restrict__ src, const int* __restrict__ dst)
{
    int i = blockIdx.x * 256 + threadIdx.x;
    if (i >= N_EDGES) return;
    int d = dst[i];
    int p = atomicAdd(&g_fill[d], 1);
    g_csr_src[p] = src[i];
}

// ---------------- HMMA GEMM: both sides, W frags streamed from gmem ---------------
// smem: X hi/lo only (69632 B). 2 blocks/SM via __launch_bounds__(256, 2).
// 4 phases (side x n-half), acc 32 regs, A-hi cached, A-lo reloaded per phase.
#define GEMM_SMEM (2 * 128 * TSE * 2)     // 69632

__global__ void __launch_bounds__(256, 2) k_gemm_mma(
    int layer, const float* __restrict__ B_l, const float* __restrict__ B_r)
{
    extern __shared__ char sm[];
    __nv_bfloat16* Xh  = (__nv_bfloat16*)sm;
    __nv_bfloat16* Xlo = Xh + 128 * TSE;

    int tid = threadIdx.x;
    int wid = tid >> 5, lane = tid & 31;
    int row0 = blockIdx.x * 128;

    // fill X tiles (hi/lo split)
    const float4* X4 = (const float4*)g_x;
    #pragma unroll
    for (int i = 0; i < 16; i++) {
        int idx = tid + i * 256;          // 0..4095
        int r = idx >> 5, kq = idx & 31;
        float4 v = make_float4(0.f, 0.f, 0.f, 0.f);
        if (row0 + r < N_NODES) v = X4[(row0 + r) * 32 + kq];
        uint2 hp, lp;
        split4(v, hp, lp);
        *(uint2*)&Xh [r * TSE + kq * 4] = hp;
        *(uint2*)&Xlo[r * TSE + kq * 4] = lp;
    }
    __syncthreads();

    // cache A-hi fragments
    uint32_t ah[8][4];
    uint32_t abase = (uint32_t)(((wid * 16 + (lane & 15)) * TSE + ((lane >> 4) << 3)) * 2);
    uint32_t xh_u = smem_u32(Xh) + abase;
    uint32_t xl_u = smem_u32(Xlo) + abase;
    #pragma unroll
    for (int ks = 0; ks < 8; ks++) ldm4(ah[ks], xh_u + ks * 32);

    int r0g = row0 + wid * 16 + (lane >> 2);
    int c0 = (lane & 3) * 2;

    #pragma unroll
    for (int s = 0; s < 2; s++) {
        const uint4* fs = g_wfrag + (layer * 2 + s) * 4096;
        float* Y = s ? g_xr : g_xl;
        const float* B = s ? B_r : B_l;
        #pragma unroll
        for (int h = 0; h < 2; h++) {
            float acc[4][8];
            #pragma unroll
            for (int j = 0; j < 4; j++)
                #pragma unroll
                for (int q = 0; q < 8; q++) acc[j][q] = 0.f;

            #pragma unroll
            for (int ks = 0; ks < 8; ks++) {
                uint32_t alr[4];
                ldm4(alr, xl_u + ks * 32);
                uint4 fh[4], fl[4];
                #pragma unroll
                for (int j = 0; j < 4; j++) {
                    int jt = h * 4 + j;
                    fh[j] = fs[((ks * 8 + jt) * 2 + 0) * 32 + lane];
                    fl[j] = fs[((ks * 8 + jt) * 2 + 1) * 32 + lane];
                }
                #pragma unroll
                for (int j = 0; j < 4; j++) {
                    mma16816(acc[j] + 0, ah[ks], fh[j].x, fh[j].y);
                    mma16816(acc[j] + 4, ah[ks], fh[j].z, fh[j].w);
                }
                #pragma unroll
                for (int j = 0; j < 4; j++) {
                    mma16816(acc[j] + 0, alr, fh[j].x, fh[j].y);
                    mma16816(acc[j] + 4, alr, fh[j].z, fh[j].w);
                }
                #pragma unroll
                for (int j = 0; j < 4; j++) {
                    mma16816(acc[j] + 0, ah[ks], fl[j].x, fl[j].y);
                    mma16816(acc[j] + 4, ah[ks], fl[j].z, fl[j].w);
                }
            }

            // epilogue
            #pragma unroll
            for (int j = 0; j < 4; j++) {
                int colA = (h * 4 + j) * 16 + c0;
                int colB = colA + 8;
                float bA0 = B[colA], bA1 = B[colA + 1];
                float bB0 = B[colB], bB1 = B[colB + 1];
                if (r0g < N_NODES) {
                    *(float2*)&Y[r0g * D + colA] =
                        make_float2(acc[j][0] + bA0, acc[j][1] + bA1);
                    *(float2*)&Y[r0g * D + colB] =
                        make_float2(acc[j][4] + bB0, acc[j][5] + bB1);
                }
                if (r0g + 8 < N_NODES) {
                    *(float2*)&Y[(r0g + 8) * D + colA] =
                        make_float2(acc[j][2] + bA0, acc[j][3] + bA1);
                    *(float2*)&Y[(r0g + 8) * D + colB] =
                        make_float2(acc[j][6] + bB0, acc[j][7] + bB1);
                }
            }
        }
    }
}

// ---------------- fused GATv2 layer: warp per node, online softmax ----------------
__global__ void __launch_bounds__(256) k_gat(
    const float* __restrict__ att, const float* __restrict__ gat_bias,
    const float* __restrict__ lng, const float* __restrict__ lnb,
    float* __restrict__ final_out, int last)
{
    int n = (blockIdx.x * 256 + threadIdx.x) >> 5;
    int lane = threadIdx.x & 31;
    if (n >= N_NODES) return;

    const float4* xl4 = (const float4*)g_xl;
    float4 xr = ((const float4*)g_xr)[n * 32 + lane];
    float4 at = ((const float4*)att)[lane];

    int e0 = g_rowptr[n];
    int e1 = g_rowptr[n + 1];

    float m = -3.402823466e+38f;
    float s = 0.f;
    float4 acc = make_float4(0.f, 0.f, 0.f, 0.f);

    int sidx = g_csr_src[e0];
    float4 a = xl4[sidx * 32 + lane];

    for (int e = e0; e < e1; e++) {
        float4 cur = a;
        if (e + 1 < e1) {
            int nx = g_csr_src[e + 1];
            a = xl4[nx * 32 + lane];
        }
        float p = leaky(cur.x + xr.x) * at.x + leaky(cur.y + xr.y) * at.y
                + leaky(cur.z + xr.z) * at.z + leaky(cur.w + xr.w) * at.w;
        p += __shfl_xor_sync(0xffffffffu, p, 4);
        p += __shfl_xor_sync(0xffffffffu, p, 2);
        p += __shfl_xor_sync(0xffffffffu, p, 1);

        float nm = fmaxf(m, p);
        float wo = __expf(m - nm);
        float wn = __expf(p - nm);
        acc.x = acc.x * wo + cur.x * wn;
        acc.y = acc.y * wo + cur.y * wn;
        acc.z = acc.z * wo + cur.z * wn;
        acc.w = acc.w * wo + cur.w * wn;
        s = s * wo + wn;
        m = nm;
    }

    float inv = 1.f / s;
    float4 gb   = ((const float4*)gat_bias)[lane];
    float4 xres = ((const float4*)g_x)[n * 32 + lane];
    float4 v;
    v.x = acc.x * inv + gb.x + xres.x;
    v.y = acc.y * inv + gb.y + xres.y;
    v.z = acc.z * inv + gb.z + xres.z;
    v.w = acc.w * inv + gb.w + xres.w;

    float sum = warp_sum(v.x + v.y + v.z + v.w);
    float ssq = warp_sum(v.x * v.x + v.y * v.y + v.z * v.z + v.w * v.w);
    float mu  = sum * (1.f / D);
    float var = ssq * (1.f / D) - mu * mu;
    float r   = rsqrtf(var + LN_EPS);

    float4 lg = ((const float4*)lng)[lane];
    float4 lb = ((const float4*)lnb)[lane];
    float4 y;
    y.x = fmaxf((v.x - mu) * r * lg.x + lb.x, 0.f);
    y.y = fmaxf((v.y - mu) * r * lg.y + lb.y, 0.f);
    y.z = fmaxf((v.z - mu) * r * lg.z + lb.z, 0.f);
    y.w = fmaxf((v.w - mu) * r * lg.w + lb.w, 0.f);

    float4* dstp = last ? (float4*)final_out : (float4*)g_x;
    dstp[n * 32 + lane] = y;
}

// ---------------- launch ----------------
extern "C" void kernel_launch(void* const* d_in, const int* in_sizes, int n_in,
                              void* d_out, int out_size)
{
    const int*   node_types = (const int*)d_in[0];
    const int*   edge_index = (const int*)d_in[1];
    const int*   src  = edge_index;
    const int*   dst  = edge_index + N_EDGES;
    const float* emb   = (const float*)d_in[2];
    const float* pW    = (const float*)d_in[3];
    const float* pb    = (const float*)d_in[4];
    const float* pg    = (const float*)d_in[5];
    const float* pbeta = (const float*)d_in[6];
    const float* Wl    = (const float*)d_in[7];
    const float* bl    = (const float*)d_in[8];
    const float* Wr    = (const float*)d_in[9];
    const float* br    = (const float*)d_in[10];
    const float* att   = (const float*)d_in[11];
    const float* gbias = (const float*)d_in[12];
    const float* lng   = (const float*)d_in[13];
    const float* lnb   = (const float*)d_in[14];
    float* out = (float*)d_out;

    cudaFuncSetAttribute(k_gemm_mma, cudaFuncAttributeMaxDynamicSharedMemorySize,
                         GEMM_SMEM);

    const int gemm_blocks = (N_NODES + 127) / 128;   // 391
    const int gat_blocks  = (N_NODES * 32 + 255) / 256;

    // launch order chosen so layer-0 GEMM is launch index 3 (profiled by ncu)
    k_wprep_deg<<<128, 256>>>(Wl, Wr);                       // 0: W frags + deg init
    k_embed_proj<<<N_NODES, 128>>>(node_types, emb, pW, pb, pg, pbeta); // 1
    k_hist<<<(N_EDGES + 255) / 256, 256>>>(dst);             // 2
    k_gemm_mma<<<gemm_blocks, 256, GEMM_SMEM>>>(0, bl, br);  // 3  <-- profiled
    k_scan1<<<NB, 256>>>();                                  // 4
    k_scan2<<<1, 256>>>();                                   // 5
    k_build<<<NB, 256>>>();                                  // 6
    k_scatter<<<(N_EDGES + 255) / 256, 256>>>(src, dst);     // 7

    for (int l = 0; l < LAYERS; l++) {
        if (l > 0)
            k_gemm_mma<<<gemm_blocks, 256, GEMM_SMEM>>>(l, bl + l * D, br + l * D);
        k_gat<<<gat_blocks, 256>>>(att + l * H * C, gbias + l * D,
                                   lng + l * D, lnb + l * D,
                                   out, l == LAYERS - 1);
    }
}

// round 7
// speedup vs baseline: 2.7923x; 1.0491x over previous
#include <cuda_runtime.h>
#include <cuda_bf16.h>
#include <cstdint>

#define N_NODES 50000
#define N_EDGES 600000
#define ETOT    650000           // edges + self loops
#define D       128
#define H       4
#define C       32
#define LAYERS  4
#define LN_EPS  1e-5f
#define SLOPE   0.2f
#define NB      196              // scan blocks: ceil(50000/256)
#define TSE     136              // padded smem row stride (bf16 elems)

// ---------------- scratch (device globals; no allocations) ----------------
__device__ float g_x[N_NODES * D];        // current node features
__device__ float g_xl[N_NODES * D];       // x @ Wl + bl
__device__ float g_xr[N_NODES * D];       // x @ Wr + br
__device__ int   g_deg[N_NODES];          // degree (incl. self loop)
__device__ int   g_rowptr[N_NODES + 1];
__device__ int   g_fill[N_NODES];
__device__ int   g_csr_src[ETOT];         // src node per CSR slot
__device__ int   g_bsum[256];             // scan block partials
// pre-computed mma B-fragments: [l][s][ks][jt][hl][lane] -> uint4 (4 frag regs)
__device__ uint4 g_wfrag[LAYERS * 2 * 4096];

__device__ __forceinline__ float leaky(float v) {
    return v > 0.f ? v : v * SLOPE;
}

__device__ __forceinline__ float warp_sum(float v) {
    #pragma unroll
    for (int o = 16; o > 0; o >>= 1) v += __shfl_xor_sync(0xffffffffu, v, o);
    return v;
}

__device__ __forceinline__ uint32_t smem_u32(const void* p) {
    uint32_t a;
    asm("{ .reg .u64 t; cvta.to.shared.u64 t, %1; cvt.u32.u64 %0, t; }"
        : "=r"(a) : "l"(p));
    return a;
}

// ---------------- tensor-core primitives (arch-portable PTX) ----------------
__device__ __forceinline__ void ldm4(uint32_t* r, uint32_t addr) {
    asm volatile("ldmatrix.sync.aligned.m8n8.x4.shared.b16 {%0,%1,%2,%3}, [%4];"
                 : "=r"(r[0]), "=r"(r[1]), "=r"(r[2]), "=r"(r[3]) : "r"(addr));
}

__device__ __forceinline__ void mma16816(float* d, const uint32_t* a,
                                         uint32_t b0, uint32_t b1) {
    asm volatile(
        "mma.sync.aligned.m16n8k16.row.col.f32.bf16.bf16.f32 "
        "{%0,%1,%2,%3}, {%4,%5,%6,%7}, {%8,%9}, {%0,%1,%2,%3};"
        : "+f"(d[0]), "+f"(d[1]), "+f"(d[2]), "+f"(d[3])
        : "r"(a[0]), "r"(a[1]), "r"(a[2]), "r"(a[3]), "r"(b0), "r"(b1));
}

// hi/lo bf16 split pack
__device__ __forceinline__ void split4(float4 v, uint2& hp, uint2& lp) {
    __nv_bfloat16 h0 = __float2bfloat16_rn(v.x);
    __nv_bfloat16 h1 = __float2bfloat16_rn(v.y);
    __nv_bfloat16 h2 = __float2bfloat16_rn(v.z);
    __nv_bfloat16 h3 = __float2bfloat16_rn(v.w);
    __nv_bfloat16 l0 = __float2bfloat16_rn(v.x - __bfloat162float(h0));
    __nv_bfloat16 l1 = __float2bfloat16_rn(v.y - __bfloat162float(h1));
    __nv_bfloat16 l2 = __float2bfloat16_rn(v.z - __bfloat162float(h2));
    __nv_bfloat16 l3 = __float2bfloat16_rn(v.w - __bfloat162float(h3));
    hp.x = (uint32_t)__bfloat16_as_ushort(h0) | ((uint32_t)__bfloat16_as_ushort(h1) << 16);
    hp.y = (uint32_t)__bfloat16_as_ushort(h2) | ((uint32_t)__bfloat16_as_ushort(h3) << 16);
    lp.x = (uint32_t)__bfloat16_as_ushort(l0) | ((uint32_t)__bfloat16_as_ushort(l1) << 16);
    lp.y = (uint32_t)__bfloat16_as_ushort(l2) | ((uint32_t)__bfloat16_as_ushort(l3) << 16);
}

// pack one (hi or lo) bf16 pair from two floats
__device__ __forceinline__ uint32_t pack_hl(float a, float b, int hl) {
    __nv_bfloat16 ha = __float2bfloat16_rn(a);
    __nv_bfloat16 hb = __float2bfloat16_rn(b);
    if (hl) {
        ha = __float2bfloat16_rn(a - __bfloat162float(ha));
        hb = __float2bfloat16_rn(b - __bfloat162float(hb));
    }
    return (uint32_t)__bfloat16_as_ushort(ha) |
           ((uint32_t)__bfloat16_as_ushort(hb) << 16);
}

// ---------------- W fragment prep (all layers) + deg init ----------------
__global__ void __launch_bounds__(256) k_wprep_deg(const float* __restrict__ Wl,
                                                   const float* __restrict__ Wr)
{
    int t = blockIdx.x * 256 + threadIdx.x;     // 0..32767
    if (t < N_NODES) g_deg[t] = 1;
    int t2 = t + 32768;
    if (t2 < N_NODES) g_deg[t2] = 1;

    int lane = t & 31;
    int hl   = (t >> 5) & 1;
    int jt   = (t >> 6) & 7;
    int ks   = (t >> 9) & 7;
    int s    = (t >> 12) & 1;
    int l    = (t >> 13) & 3;

    const float* W = (s ? Wr : Wl) + (size_t)l * D * D;
    int n0 = jt * 16 + (lane >> 2);
    int k0 = ks * 16 + 2 * (lane & 3);
    uint4 f;
    f.x = pack_hl(W[(k0 + 0) * D + n0],     W[(k0 + 1) * D + n0],     hl);
    f.y = pack_hl(W[(k0 + 8) * D + n0],     W[(k0 + 9) * D + n0],     hl);
    f.z = pack_hl(W[(k0 + 0) * D + n0 + 8], W[(k0 + 1) * D + n0 + 8], hl);
    f.w = pack_hl(W[(k0 + 8) * D + n0 + 8], W[(k0 + 9) * D + n0 + 8], hl);
    g_wfrag[(((((l * 2 + s) * 8 + ks) * 8 + jt) * 2 + hl) * 32) + lane] = f;
}

// ---------------- kernel 0: embedding + input projection + LN + ReLU ----------------
__global__ void __launch_bounds__(128) k_embed_proj(
    const int* __restrict__ types, const float* __restrict__ emb,
    const float* __restrict__ Wp, const float* __restrict__ bp,
    const float* __restrict__ gp, const float* __restrict__ betap)
{
    int n = blockIdx.x;
    int t = threadIdx.x;
    int ty = types[n];

    float acc = bp[t];
    #pragma unroll
    for (int k = 0; k < 16; k++)
        acc += emb[ty * 16 + k] * Wp[k * D + t];

    __shared__ float s1[4], s2[4];
    int lane = t & 31, warp = t >> 5;
    float w1 = warp_sum(acc), w2 = warp_sum(acc * acc);
    if (lane == 0) { s1[warp] = w1; s2[warp] = w2; }
    __syncthreads();
    float sum = s1[0] + s1[1] + s1[2] + s1[3];
    float ssq = s2[0] + s2[1] + s2[2] + s2[3];
    float mu  = sum * (1.f / D);
    float var = ssq * (1.f / D) - mu * mu;
    float y = (acc - mu) * rsqrtf(var + LN_EPS) * gp[t] + betap[t];
    g_x[n * D + t] = fmaxf(y, 0.f);
}

// ---------------- CSR build ----------------
__global__ void __launch_bounds__(256) k_hist(const int* __restrict__ dst)
{
    int i = blockIdx.x * 256 + threadIdx.x;
    if (i < N_EDGES) atomicAdd(&g_deg[dst[i]], 1);
}

__global__ void __launch_bounds__(256) k_scan1()
{
    __shared__ int ws[8];
    int t = threadIdx.x, lane = t & 31, w = t >> 5;
    int i = blockIdx.x * 256 + t;
    int v = (i < N_NODES) ? g_deg[i] : 0;
    int x = v;
    #pragma unroll
    for (int o = 1; o < 32; o <<= 1) {
        int y = __shfl_up_sync(0xffffffffu, x, o);
        if (lane >= o) x += y;
    }
    if (lane == 31) ws[w] = x;
    __syncthreads();
    if (t == 0) {
        int run = 0;
        #pragma unroll
        for (int j = 0; j < 8; j++) { int tmp = ws[j]; ws[j] = run; run += tmp; }
        g_bsum[blockIdx.x] = run;
    }
    __syncthreads();
    if (i < N_NODES) g_rowptr[i] = ws[w] + (x - v);
}

__global__ void __launch_bounds__(256) k_scan2()
{
    __shared__ int ws[8];
    int t = threadIdx.x, lane = t & 31, w = t >> 5;
    int v = (t < NB) ? g_bsum[t] : 0;
    int x = v;
    #pragma unroll
    for (int o = 1; o < 32; o <<= 1) {
        int y = __shfl_up_sync(0xffffffffu, x, o);
        if (lane >= o) x += y;
    }
    if (lane == 31) ws[w] = x;
    __syncthreads();
    if (t == 0) {
        int run = 0;
        #pragma unroll
        for (int j = 0; j < 8; j++) { int tmp = ws[j]; ws[j] = run; run += tmp; }
        g_rowptr[N_NODES] = ETOT;
    }
    __syncthreads();
    g_bsum[t] = ws[w] + (x - v);
}

__global__ void __launch_bounds__(256) k_build()
{
    int i = blockIdx.x * 256 + threadIdx.x;
    if (i >= N_NODES) return;
    int excl = g_rowptr[i] + g_bsum[i >> 8];
    g_rowptr[i] = excl;
    g_csr_src[excl] = i;                  // self loop first
    g_fill[i] = excl + 1;
}

__global__ void __launch_bounds__(256) k_scatter(
    const int* __restrict__ src, const int* __restrict__ dst)
{
    int i = blockIdx.x * 256 + threadIdx.x;
    if (i >= N_EDGES) return;
    int d = dst[i];
    int p = atomicAdd(&g_fill[d], 1);
    g_csr_src[p] = src[i];
}

// ---------------- HMMA GEMM: both sides, 3 blocks/SM (single wave) ---------------
// smem: X hi/lo only (69632 B); W frags streamed from gmem (L1-resident).
// No A-frag register cache (re-ldmatrix per phase) to fit 84-reg budget.
#define GEMM_SMEM (2 * 128 * TSE * 2)     // 69632

__global__ void __launch_bounds__(256, 3) k_gemm_mma(
    int layer, const float* __restrict__ B_l, const float* __restrict__ B_r)
{
    extern __shared__ char sm[];
    __nv_bfloat16* Xh  = (__nv_bfloat16*)sm;
    __nv_bfloat16* Xlo = Xh + 128 * TSE;

    int tid = threadIdx.x;
    int wid = tid >> 5, lane = tid & 31;
    int row0 = blockIdx.x * 128;

    // fill X tiles (hi/lo split)
    const float4* X4 = (const float4*)g_x;
    #pragma unroll
    for (int i = 0; i < 16; i++) {
        int idx = tid + i * 256;          // 0..4095
        int r = idx >> 5, kq = idx & 31;
        float4 v = make_float4(0.f, 0.f, 0.f, 0.f);
        if (row0 + r < N_NODES) v = X4[(row0 + r) * 32 + kq];
        uint2 hp, lp;
        split4(v, hp, lp);
        *(uint2*)&Xh [r * TSE + kq * 4] = hp;
        *(uint2*)&Xlo[r * TSE + kq * 4] = lp;
    }
    __syncthreads();

    uint32_t abase = (uint32_t)(((wid * 16 + (lane & 15)) * TSE + ((lane >> 4) << 3)) * 2);
    uint32_t xh_u = smem_u32(Xh) + abase;
    uint32_t xl_u = smem_u32(Xlo) + abase;

    int r0g = row0 + wid * 16 + (lane >> 2);
    int c0 = (lane & 3) * 2;

    #pragma unroll
    for (int s = 0; s < 2; s++) {
        const uint4* fs = g_wfrag + (layer * 2 + s) * 4096;
        float* Y = s ? g_xr : g_xl;
        const float* B = s ? B_r : B_l;
        #pragma unroll
        for (int h = 0; h < 2; h++) {
            float acc[4][8];
            #pragma unroll
            for (int j = 0; j < 4; j++)
                #pragma unroll
                for (int q = 0; q < 8; q++) acc[j][q] = 0.f;

            #pragma unroll
            for (int ks = 0; ks < 8; ks++) {
                uint32_t ah[4], al[4];
                ldm4(ah, xh_u + ks * 32);
                ldm4(al, xl_u + ks * 32);
                #pragma unroll
                for (int j = 0; j < 4; j++) {
                    int jt = h * 4 + j;
                    uint4 fh = fs[((ks * 8 + jt) * 2 + 0) * 32 + lane];
                    uint4 fl = fs[((ks * 8 + jt) * 2 + 1) * 32 + lane];
                    mma16816(acc[j] + 0, ah, fh.x, fh.y);
                    mma16816(acc[j] + 4, ah, fh.z, fh.w);
                    mma16816(acc[j] + 0, al, fh.x, fh.y);
                    mma16816(acc[j] + 4, al, fh.z, fh.w);
                    mma16816(acc[j] + 0, ah, fl.x, fl.y);
                    mma16816(acc[j] + 4, ah, fl.z, fl.w);
                }
            }

            // epilogue
            #pragma unroll
            for (int j = 0; j < 4; j++) {
                int colA = (h * 4 + j) * 16 + c0;
                int colB = colA + 8;
                float bA0 = B[colA], bA1 = B[colA + 1];
                float bB0 = B[colB], bB1 = B[colB + 1];
                if (r0g < N_NODES) {
                    *(float2*)&Y[r0g * D + colA] =
                        make_float2(acc[j][0] + bA0, acc[j][1] + bA1);
                    *(float2*)&Y[r0g * D + colB] =
                        make_float2(acc[j][4] + bB0, acc[j][5] + bB1);
                }
                if (r0g + 8 < N_NODES) {
                    *(float2*)&Y[(r0g + 8) * D + colA] =
                        make_float2(acc[j][2] + bA0, acc[j][3] + bA1);
                    *(float2*)&Y[(r0g + 8) * D + colB] =
                        make_float2(acc[j][6] + bB0, acc[j][7] + bB1);
                }
            }
        }
    }
}

// ---------------- fused GATv2 layer: warp per node, online softmax ----------------
__global__ void __launch_bounds__(256) k_gat(
    const float* __restrict__ att, const float* __restrict__ gat_bias,
    const float* __restrict__ lng, const float* __restrict__ lnb,
    float* __restrict__ final_out, int last)
{
    int n = (blockIdx.x * 256 + threadIdx.x) >> 5;
    int lane = threadIdx.x & 31;
    if (n >= N_NODES) return;

    const float4* xl4 = (const float4*)g_xl;
    float4 xr = ((const float4*)g_xr)[n * 32 + lane];
    float4 at = ((const float4*)att)[lane];

    int e0 = g_rowptr[n];
    int e1 = g_rowptr[n + 1];

    float m = -3.402823466e+38f;
    float s = 0.f;
    float4 acc = make_float4(0.f, 0.f, 0.f, 0.f);

    int sidx = g_csr_src[e0];
    float4 a = xl4[sidx * 32 + lane];

    for (int e = e0; e < e1; e++) {
        float4 cur = a;
        if (e + 1 < e1) {
            int nx = g_csr_src[e + 1];
            a = xl4[nx * 32 + lane];
        }
        float p = leaky(cur.x + xr.x) * at.x + leaky(cur.y + xr.y) * at.y
                + leaky(cur.z + xr.z) * at.z + leaky(cur.w + xr.w) * at.w;
        p += __shfl_xor_sync(0xffffffffu, p, 4);
        p += __shfl_xor_sync(0xffffffffu, p, 2);
        p += __shfl_xor_sync(0xffffffffu, p, 1);

        float nm = fmaxf(m, p);
        float wo = __expf(m - nm);
        float wn = __expf(p - nm);
        acc.x = acc.x * wo + cur.x * wn;
        acc.y = acc.y * wo + cur.y * wn;
        acc.z = acc.z * wo + cur.z * wn;
        acc.w = acc.w * wo + cur.w * wn;
        s = s * wo + wn;
        m = nm;
    }

    float inv = 1.f / s;
    float4 gb   = ((const float4*)gat_bias)[lane];
    float4 xres = ((const float4*)g_x)[n * 32 + lane];
    float4 v;
    v.x = acc.x * inv + gb.x + xres.x;
    v.y = acc.y * inv + gb.y + xres.y;
    v.z = acc.z * inv + gb.z + xres.z;
    v.w = acc.w * inv + gb.w + xres.w;

    float sum = warp_sum(v.x + v.y + v.z + v.w);
    float ssq = warp_sum(v.x * v.x + v.y * v.y + v.z * v.z + v.w * v.w);
    float mu  = sum * (1.f / D);
    float var = ssq * (1.f / D) - mu * mu;
    float r   = rsqrtf(var + LN_EPS);

    float4 lg = ((const float4*)lng)[lane];
    float4 lb = ((const float4*)lnb)[lane];
    float4 y;
    y.x = fmaxf((v.x - mu) * r * lg.x + lb.x, 0.f);
    y.y = fmaxf((v.y - mu) * r * lg.y + lb.y, 0.f);
    y.z = fmaxf((v.z - mu) * r * lg.z + lb.z, 0.f);
    y.w = fmaxf((v.w - mu) * r * lg.w + lb.w, 0.f);

    float4* dstp = last ? (float4*)final_out : (float4*)g_x;
    dstp[n * 32 + lane] = y;
}

// ---------------- launch ----------------
extern "C" void kernel_launch(void* const* d_in, const int* in_sizes, int n_in,
                              void* d_out, int out_size)
{
    const int*   node_types = (const int*)d_in[0];
    const int*   edge_index = (const int*)d_in[1];
    const int*   src  = edge_index;
    const int*   dst  = edge_index + N_EDGES;
    const float* emb   = (const float*)d_in[2];
    const float* pW    = (const float*)d_in[3];
    const float* pb    = (const float*)d_in[4];
    const float* pg    = (const float*)d_in[5];
    const float* pbeta = (const float*)d_in[6];
    const float* Wl    = (const float*)d_in[7];
    const float* bl    = (const float*)d_in[8];
    const float* Wr    = (const float*)d_in[9];
    const float* br    = (const float*)d_in[10];
    const float* att   = (const float*)d_in[11];
    const float* gbias = (const float*)d_in[12];
    const float* lng   = (const float*)d_in[13];
    const float* lnb   = (const float*)d_in[14];
    float* out = (float*)d_out;

    cudaFuncSetAttribute(k_gemm_mma, cudaFuncAttributeMaxDynamicSharedMemorySize,
                         GEMM_SMEM);

    const int gemm_blocks = (N_NODES + 127) / 128;   // 391
    const int gat_blocks  = (N_NODES * 32 + 255) / 256;

    // launch order chosen so layer-0 GEMM is launch index 3 (profiled by ncu)
    k_wprep_deg<<<128, 256>>>(Wl, Wr);                       // 0: W frags + deg init
    k_embed_proj<<<N_NODES, 128>>>(node_types, emb, pW, pb, pg, pbeta); // 1
    k_hist<<<(N_EDGES + 255) / 256, 256>>>(dst);             // 2
    k_gemm_mma<<<gemm_blocks, 256, GEMM_SMEM>>>(0, bl, br);  // 3  <-- profiled
    k_scan1<<<NB, 256>>>();                                  // 4
    k_scan2<<<1, 256>>>();                                   // 5
    k_build<<<NB, 256>>>();                                  // 6
    k_scatter<<<(N_EDGES + 255) / 256, 256>>>(src, dst);     // 7

    for (int l = 0; l < LAYERS; l++) {
        if (l > 0)
            k_gemm_mma<<<gemm_blocks, 256, GEMM_SMEM>>>(l, bl + l * D, br + l * D);
        k_gat<<<gat_blocks, 256>>>(att + l * H * C, gbias + l * D,
                                   lng + l * D, lnb + l * D,
                                   out, l == LAYERS - 1);
    }
}